// round 1
// baseline (speedup 1.0000x reference)
#include <cuda_runtime.h>
#include <cuda_bf16.h>
#include <cstdint>

// Problem constants
#define Bb 2
#define Ss 2048
#define Dd 2048
#define Hh 16
#define HDd 128
#define MROWS (Bb*Ss)              // 4096
#define ATTN_SCALE 0.08838834764831845f  // 1/sqrt(128)

// Scratch (static device globals: allocation-free rule)
__device__ float g_Q[(size_t)MROWS*Dd];
__device__ float g_K[(size_t)MROWS*Dd];
__device__ float g_V[(size_t)MROWS*Dd];
__device__ float g_A[(size_t)MROWS*Dd];

__device__ __forceinline__ float to_tf32f(float x){
    uint32_t u; asm("cvt.rna.tf32.f32 %0, %1;" : "=r"(u) : "f"(x));
    return __uint_as_float(u);
}

__device__ __forceinline__ void mma_tf32(float c[4], const uint32_t a[4],
                                         uint32_t b0, uint32_t b1){
    asm volatile("mma.sync.aligned.m16n8k8.row.col.f32.tf32.tf32.f32 "
        "{%0,%1,%2,%3}, {%4,%5,%6,%7}, {%8,%9}, {%0,%1,%2,%3};\n"
        : "+f"(c[0]), "+f"(c[1]), "+f"(c[2]), "+f"(c[3])
        : "r"(a[0]), "r"(a[1]), "r"(a[2]), "r"(a[3]), "r"(b0), "r"(b1));
}

// ============================================================
// GEMM: C[M,N] = A[M,K] * W[N,K]^T   (tf32 mma, 128x128x32 tiles)
// ============================================================
#define TM 128
#define TN 128
#define TK 32
#define APAD 36   // pad so fragment-load pattern (addr ≡ 4g+t mod 32) is conflict-free

__global__ __launch_bounds__(256) void gemm_nt(const float* __restrict__ A,
                                               const float* __restrict__ W,
                                               float* __restrict__ C,
                                               int M, int N, int K)
{
    __shared__ float As[TM*APAD];
    __shared__ float Ws[TN*APAD];
    const int tid  = threadIdx.x;
    const int lane = tid & 31, warp = tid >> 5;
    const int wm = warp >> 1, wn = warp & 1;      // 4x2 warp grid
    const int g = lane >> 2, t = lane & 3;
    const int bM = blockIdx.y * TM, bN = blockIdx.x * TN;

    float acc[2][8][4];
    #pragma unroll
    for (int i = 0; i < 2; i++)
        #pragma unroll
        for (int j = 0; j < 8; j++)
            #pragma unroll
            for (int e = 0; e < 4; e++) acc[i][j][e] = 0.f;

    for (int k0 = 0; k0 < K; k0 += TK) {
        // 1024 float4 per tile, 256 threads -> 4 each
        #pragma unroll
        for (int i = 0; i < 4; i++) {
            int idx = tid + i * 256;
            int row = idx >> 3, c4 = (idx & 7) << 2;
            float4 va = *(const float4*)&A[(size_t)(bM + row) * K + k0 + c4];
            As[row*APAD + c4+0] = to_tf32f(va.x);
            As[row*APAD + c4+1] = to_tf32f(va.y);
            As[row*APAD + c4+2] = to_tf32f(va.z);
            As[row*APAD + c4+3] = to_tf32f(va.w);
            float4 vb = *(const float4*)&W[(size_t)(bN + row) * K + k0 + c4];
            Ws[row*APAD + c4+0] = to_tf32f(vb.x);
            Ws[row*APAD + c4+1] = to_tf32f(vb.y);
            Ws[row*APAD + c4+2] = to_tf32f(vb.z);
            Ws[row*APAD + c4+3] = to_tf32f(vb.w);
        }
        __syncthreads();

        #pragma unroll
        for (int kk = 0; kk < TK; kk += 8) {
            uint32_t a[2][4];
            #pragma unroll
            for (int mt = 0; mt < 2; mt++) {
                int r = wm*32 + mt*16 + g;
                a[mt][0] = __float_as_uint(As[r*APAD     + kk + t]);
                a[mt][1] = __float_as_uint(As[(r+8)*APAD + kk + t]);
                a[mt][2] = __float_as_uint(As[r*APAD     + kk + t + 4]);
                a[mt][3] = __float_as_uint(As[(r+8)*APAD + kk + t + 4]);
            }
            #pragma unroll
            for (int nt = 0; nt < 8; nt++) {
                int nr = wn*64 + nt*8 + g;
                uint32_t b0 = __float_as_uint(Ws[nr*APAD + kk + t]);
                uint32_t b1 = __float_as_uint(Ws[nr*APAD + kk + t + 4]);
                mma_tf32(acc[0][nt], a[0], b0, b1);
                mma_tf32(acc[1][nt], a[1], b0, b1);
            }
        }
        __syncthreads();
    }

    #pragma unroll
    for (int mt = 0; mt < 2; mt++) {
        int r = bM + wm*32 + mt*16 + g;
        #pragma unroll
        for (int nt = 0; nt < 8; nt++) {
            int cb = bN + wn*64 + nt*8 + t*2;
            C[(size_t)r*N + cb]       = acc[mt][nt][0];
            C[(size_t)r*N + cb + 1]   = acc[mt][nt][1];
            C[(size_t)(r+8)*N + cb]   = acc[mt][nt][2];
            C[(size_t)(r+8)*N + cb+1] = acc[mt][nt][3];
        }
    }
}

// ============================================================
// RoPE (in place on [MROWS, D] viewed as [.., H, HD])
// ============================================================
__global__ void rope_kernel(float* __restrict__ P,
                            const float* __restrict__ cosT,
                            const float* __restrict__ sinT)
{
    int idx = blockIdx.x * blockDim.x + threadIdx.x;   // one thread per (row, h, hd<64)
    int hd  = idx & 63;
    int h   = (idx >> 6) & (Hh - 1);
    int row = idx >> 10;
    int s   = row & (Ss - 1);
    size_t base = (size_t)row * Dd + h * HDd;
    float q1 = P[base + hd], q2 = P[base + hd + 64];
    float c1 = cosT[s*HDd + hd],      s1 = sinT[s*HDd + hd];
    float c2 = cosT[s*HDd + hd + 64], s2 = sinT[s*HDd + hd + 64];
    P[base + hd]      = q1 * c1 - q2 * s1;   // q*cos + (-x2)*sin
    P[base + hd + 64] = q2 * c2 + q1 * s2;   // q*cos + ( x1)*sin
}

// ============================================================
// Flash attention: 64-query tile per block, 64-key tiles, causal.
// 4 warps, each owns 16 query rows. tf32 mma for QK^T and PV.
// ============================================================
#define QT 64
#define KT 64
#define QPAD 132   // 128 + 4 pad (conflict-free fragment pattern)
#define PPAD 68    // 64 + 4 pad
#define ATTN_SMEM ((QT*QPAD + 2*KT*QPAD + QT*PPAD) * 4)   // 118784 B

__global__ __launch_bounds__(128) void attn_kernel()
{
    extern __shared__ float sm[];
    float* Qs = sm;                    // [QT][QPAD]
    float* Ks = Qs + QT*QPAD;          // [KT][QPAD]
    float* Vs = Ks + KT*QPAD;          // [KT][QPAD]
    float* Ps = Vs + KT*QPAD;          // [QT][PPAD]

    const int tid  = threadIdx.x;
    const int lane = tid & 31, warp = tid >> 5;
    const int g = lane >> 2, t = lane & 3;
    const int qtile = blockIdx.x;
    const int bh = blockIdx.y;
    const int b  = bh >> 4, h = bh & 15;
    const int q0 = qtile * QT;

    // Load Q tile (64 x 128)
    const size_t qgbase = (size_t)(b*Ss + q0) * Dd + h * HDd;
    #pragma unroll
    for (int i = 0; i < 16; i++) {
        int idx = tid + i * 128;           // 2048 float4
        int r = idx >> 5, c4 = (idx & 31) << 2;
        float4 v = *(const float4*)&g_Q[qgbase + (size_t)r*Dd + c4];
        Qs[r*QPAD + c4+0] = to_tf32f(v.x);
        Qs[r*QPAD + c4+1] = to_tf32f(v.y);
        Qs[r*QPAD + c4+2] = to_tf32f(v.z);
        Qs[r*QPAD + c4+3] = to_tf32f(v.w);
    }

    float accO[16][4];
    #pragma unroll
    for (int nt = 0; nt < 16; nt++)
        #pragma unroll
        for (int e = 0; e < 4; e++) accO[nt][e] = 0.f;
    float m0 = -INFINITY, m1 = -INFINITY, l0 = 0.f, l1 = 0.f;

    const int row0 = q0 + warp*16 + g;
    const int row1 = row0 + 8;

    for (int j = 0; j <= q0; j += KT) {
        __syncthreads();   // prior PV done before overwriting K/V
        #pragma unroll
        for (int i = 0; i < 16; i++) {
            int idx = tid + i * 128;
            int r = idx >> 5, c4 = (idx & 31) << 2;
            size_t gb = (size_t)(b*Ss + j + r) * Dd + h * HDd + c4;
            float4 vk = *(const float4*)&g_K[gb];
            Ks[r*QPAD + c4+0] = to_tf32f(vk.x);
            Ks[r*QPAD + c4+1] = to_tf32f(vk.y);
            Ks[r*QPAD + c4+2] = to_tf32f(vk.z);
            Ks[r*QPAD + c4+3] = to_tf32f(vk.w);
            float4 vv = *(const float4*)&g_V[gb];
            Vs[r*QPAD + c4+0] = to_tf32f(vv.x);
            Vs[r*QPAD + c4+1] = to_tf32f(vv.y);
            Vs[r*QPAD + c4+2] = to_tf32f(vv.z);
            Vs[r*QPAD + c4+3] = to_tf32f(vv.w);
        }
        __syncthreads();

        // ---- scores = Q K^T (warp: 16 x 64) ----
        float sc[8][4];
        #pragma unroll
        for (int nt = 0; nt < 8; nt++)
            #pragma unroll
            for (int e = 0; e < 4; e++) sc[nt][e] = 0.f;

        #pragma unroll
        for (int kk = 0; kk < HDd; kk += 8) {
            uint32_t a[4];
            int r = warp*16 + g;
            a[0] = __float_as_uint(Qs[r*QPAD     + kk + t]);
            a[1] = __float_as_uint(Qs[(r+8)*QPAD + kk + t]);
            a[2] = __float_as_uint(Qs[r*QPAD     + kk + t + 4]);
            a[3] = __float_as_uint(Qs[(r+8)*QPAD + kk + t + 4]);
            #pragma unroll
            for (int nt = 0; nt < 8; nt++) {
                int nr = nt*8 + g;
                uint32_t b0 = __float_as_uint(Ks[nr*QPAD + kk + t]);
                uint32_t b1 = __float_as_uint(Ks[nr*QPAD + kk + t + 4]);
                mma_tf32(sc[nt], a, b0, b1);
            }
        }

        // ---- scale + causal mask (only diagonal tile needs it) ----
        const bool diag = (j == q0);
        #pragma unroll
        for (int nt = 0; nt < 8; nt++) {
            int col = j + nt*8 + t*2;
            sc[nt][0] *= ATTN_SCALE; sc[nt][1] *= ATTN_SCALE;
            sc[nt][2] *= ATTN_SCALE; sc[nt][3] *= ATTN_SCALE;
            if (diag) {
                if (col     > row0) sc[nt][0] = -INFINITY;
                if (col + 1 > row0) sc[nt][1] = -INFINITY;
                if (col     > row1) sc[nt][2] = -INFINITY;
                if (col + 1 > row1) sc[nt][3] = -INFINITY;
            }
        }

        // ---- online softmax ----
        float rm0 = -INFINITY, rm1 = -INFINITY;
        #pragma unroll
        for (int nt = 0; nt < 8; nt++) {
            rm0 = fmaxf(rm0, fmaxf(sc[nt][0], sc[nt][1]));
            rm1 = fmaxf(rm1, fmaxf(sc[nt][2], sc[nt][3]));
        }
        rm0 = fmaxf(rm0, __shfl_xor_sync(0xffffffffu, rm0, 1));
        rm0 = fmaxf(rm0, __shfl_xor_sync(0xffffffffu, rm0, 2));
        rm1 = fmaxf(rm1, __shfl_xor_sync(0xffffffffu, rm1, 1));
        rm1 = fmaxf(rm1, __shfl_xor_sync(0xffffffffu, rm1, 2));

        float m0n = fmaxf(m0, rm0), m1n = fmaxf(m1, rm1);
        float al0 = __expf(m0 - m0n), al1 = __expf(m1 - m1n);
        float sum0 = 0.f, sum1 = 0.f;
        int pr0 = warp*16 + g, pr1 = pr0 + 8;
        #pragma unroll
        for (int nt = 0; nt < 8; nt++) {
            int cb = nt*8 + t*2;
            float p0 = __expf(sc[nt][0] - m0n);
            float p1 = __expf(sc[nt][1] - m0n);
            float p2 = __expf(sc[nt][2] - m1n);
            float p3 = __expf(sc[nt][3] - m1n);
            sum0 += p0 + p1; sum1 += p2 + p3;
            Ps[pr0*PPAD + cb]     = to_tf32f(p0);
            Ps[pr0*PPAD + cb + 1] = to_tf32f(p1);
            Ps[pr1*PPAD + cb]     = to_tf32f(p2);
            Ps[pr1*PPAD + cb + 1] = to_tf32f(p3);
        }
        sum0 += __shfl_xor_sync(0xffffffffu, sum0, 1);
        sum0 += __shfl_xor_sync(0xffffffffu, sum0, 2);
        sum1 += __shfl_xor_sync(0xffffffffu, sum1, 1);
        sum1 += __shfl_xor_sync(0xffffffffu, sum1, 2);
        l0 = l0 * al0 + sum0;
        l1 = l1 * al1 + sum1;
        m0 = m0n; m1 = m1n;
        #pragma unroll
        for (int nt = 0; nt < 16; nt++) {
            accO[nt][0] *= al0; accO[nt][1] *= al0;
            accO[nt][2] *= al1; accO[nt][3] *= al1;
        }
        __syncwarp();   // Ps per-warp rows: write->read ordering

        // ---- O += P V (warp: 16 x 128) ----
        #pragma unroll
        for (int kk = 0; kk < KT; kk += 8) {
            uint32_t a[4];
            a[0] = __float_as_uint(Ps[pr0*PPAD + kk + t]);
            a[1] = __float_as_uint(Ps[pr1*PPAD + kk + t]);
            a[2] = __float_as_uint(Ps[pr0*PPAD + kk + t + 4]);
            a[3] = __float_as_uint(Ps[pr1*PPAD + kk + t + 4]);
            #pragma unroll
            for (int nt = 0; nt < 16; nt++) {
                uint32_t b0 = __float_as_uint(Vs[(kk + t)*QPAD     + nt*8 + g]);
                uint32_t b1 = __float_as_uint(Vs[(kk + t + 4)*QPAD + nt*8 + g]);
                mma_tf32(accO[nt], a, b0, b1);
            }
        }
    }

    // ---- epilogue: normalize + write [B,S,H*HD] ----
    float inv0 = 1.f / l0, inv1 = 1.f / l1;
    size_t obase = (size_t)(b*Ss + q0 + warp*16 + g) * Dd + h * HDd;
    #pragma unroll
    for (int nt = 0; nt < 16; nt++) {
        int cb = nt*8 + t*2;
        g_A[obase + cb]              = accO[nt][0] * inv0;
        g_A[obase + cb + 1]          = accO[nt][1] * inv0;
        g_A[obase + (size_t)8*Dd + cb]     = accO[nt][2] * inv1;
        g_A[obase + (size_t)8*Dd + cb + 1] = accO[nt][3] * inv1;
    }
}

// ============================================================
extern "C" void kernel_launch(void* const* d_in, const int* in_sizes, int n_in,
                              void* d_out, int out_size)
{
    (void)in_sizes; (void)n_in; (void)out_size;
    const float* x    = (const float*)d_in[0];
    // d_in[1] = mask (unused — causal implemented directly)
    const float* cosT = (const float*)d_in[2];
    const float* sinT = (const float*)d_in[3];
    const float* Wq   = (const float*)d_in[4];
    const float* Wk   = (const float*)d_in[5];
    const float* Wv   = (const float*)d_in[6];
    const float* Wo   = (const float*)d_in[7];
    float* out = (float*)d_out;

    float *qp, *kp, *vp, *ap;
    cudaGetSymbolAddress((void**)&qp, g_Q);
    cudaGetSymbolAddress((void**)&kp, g_K);
    cudaGetSymbolAddress((void**)&vp, g_V);
    cudaGetSymbolAddress((void**)&ap, g_A);

    dim3 gg(Dd / TN, MROWS / TM);   // (16, 32)
    gemm_nt<<<gg, 256>>>(x, Wq, qp, MROWS, Dd, Dd);
    gemm_nt<<<gg, 256>>>(x, Wk, kp, MROWS, Dd, Dd);
    gemm_nt<<<gg, 256>>>(x, Wv, vp, MROWS, Dd, Dd);

    int nrope = MROWS * Hh * 64;    // one thread per rotation pair
    rope_kernel<<<nrope / 256, 256>>>(qp, cosT, sinT);
    rope_kernel<<<nrope / 256, 256>>>(kp, cosT, sinT);

    cudaFuncSetAttribute(attn_kernel, cudaFuncAttributeMaxDynamicSharedMemorySize, ATTN_SMEM);
    attn_kernel<<<dim3(Ss / QT, Bb * Hh), 128, ATTN_SMEM>>>();

    gemm_nt<<<gg, 256>>>(ap, Wo, out, MROWS, Dd, Dd);
}

// round 2
// speedup vs baseline: 1.4043x; 1.4043x over previous
#include <cuda_runtime.h>
#include <cuda_bf16.h>
#include <cstdint>

// Problem constants
#define Bb 2
#define Ss 2048
#define Dd 2048
#define Hh 16
#define HDd 128
#define MROWS (Bb*Ss)              // 4096
#define ATTN_SCALE 0.08838834764831845f  // 1/sqrt(128)

// Scratch (static device globals: allocation-free rule)
__device__ float g_Q[(size_t)MROWS*Dd];
__device__ float g_K[(size_t)MROWS*Dd];
__device__ float g_V[(size_t)MROWS*Dd];
__device__ float g_A[(size_t)MROWS*Dd];

__device__ __forceinline__ float to_tf32f(float x){
    uint32_t u; asm("cvt.rna.tf32.f32 %0, %1;" : "=r"(u) : "f"(x));
    return __uint_as_float(u);
}
__device__ __forceinline__ float4 cvt4(float4 v){
    v.x = to_tf32f(v.x); v.y = to_tf32f(v.y);
    v.z = to_tf32f(v.z); v.w = to_tf32f(v.w);
    return v;
}

__device__ __forceinline__ void mma_tf32(float c[4], const uint32_t a[4],
                                         uint32_t b0, uint32_t b1){
    asm volatile("mma.sync.aligned.m16n8k8.row.col.f32.tf32.tf32.f32 "
        "{%0,%1,%2,%3}, {%4,%5,%6,%7}, {%8,%9}, {%0,%1,%2,%3};\n"
        : "+f"(c[0]), "+f"(c[1]), "+f"(c[2]), "+f"(c[3])
        : "r"(a[0]), "r"(a[1]), "r"(a[2]), "r"(a[3]), "r"(b0), "r"(b1));
}

// Swizzled smem word index for a [rows][16] tile:
// group permutation (group + row/2) & 3 keeps STS.128 fills AND scalar
// fragment loads conflict-free, with row+8 -> +128 words, row+16 -> +256 words
// (swizzle-invariant offsets usable as LDS immediates).
__device__ __forceinline__ int sidx(int row, int col){
    return row*16 + ((((col>>2) + (row>>1)) & 3) << 2) + (col & 3);
}

// ============================================================
// GEMM: C[M,N] = A[M,K] * W[N,K]^T
// 128x256 block, 8 warps (2x4) of 64x64, BK=16, 2-stage smem pipeline.
// ============================================================
#define BM 128
#define BN 256
#define BK 16
#define ASTG (BM*BK)   // 2048 words per stage
#define BSTG (BN*BK)   // 4096 words per stage

__global__ __launch_bounds__(256, 1) void gemm_nt(const float* __restrict__ A,
                                                  const float* __restrict__ W,
                                                  float* __restrict__ C,
                                                  int M, int N, int K)
{
    __shared__ float As[2*ASTG];
    __shared__ float Ws[2*BSTG];
    const int tid  = threadIdx.x;
    const int lane = tid & 31, warp = tid >> 5;
    const int wm = warp >> 2, wn = warp & 3;      // 2 x 4 warp grid
    const int g = lane >> 2, t = lane & 3;
    const int bM = blockIdx.y * BM, bN = blockIdx.x * BN;

    // ---- global load pattern: thread i -> row=i>>2, c4=(i&3)*4, rows step 64
    const int arow = tid >> 2, ac4 = (tid & 3) << 2;
    const float* Ag = A + (size_t)(bM + arow) * K + ac4;
    const float* Wg = W + (size_t)(bN + arow) * K + ac4;

    // ---- smem store offsets (float4-aligned; +64 rows = +1024 words)
    const int sA0 = sidx(arow, ac4);
    const int sB0 = sidx(arow, ac4);

    // ---- fragment base offsets within a stage (k halves kk=0 and kk=8)
    const int ar0 = wm*64 + g;
    const int br0 = wn*64 + g;
    int aof[4], bof[4];
    aof[0] = sidx(ar0,      t); aof[1] = sidx(ar0,  4 + t);
    aof[2] = sidx(ar0,  8 + t); aof[3] = sidx(ar0, 12 + t);
    bof[0] = sidx(br0,      t); bof[1] = sidx(br0,  4 + t);
    bof[2] = sidx(br0,  8 + t); bof[3] = sidx(br0, 12 + t);

    float acc[4][8][4];
    #pragma unroll
    for (int mt = 0; mt < 4; mt++)
        #pragma unroll
        for (int nt = 0; nt < 8; nt++)
            #pragma unroll
            for (int e = 0; e < 4; e++) acc[mt][nt][e] = 0.f;

    float4 ra[2], rb[4];
    // prefetch tile 0 into registers
    ra[0] = *(const float4*)(Ag);
    ra[1] = *(const float4*)(Ag + (size_t)64 * K);
    #pragma unroll
    for (int i = 0; i < 4; i++) rb[i] = *(const float4*)(Wg + (size_t)(64*i) * K);

    // fill stage 0
    *(float4*)&As[sA0]        = cvt4(ra[0]);
    *(float4*)&As[sA0 + 1024] = cvt4(ra[1]);
    #pragma unroll
    for (int i = 0; i < 4; i++) *(float4*)&Ws[sB0 + i*1024] = cvt4(rb[i]);
    __syncthreads();

    const int nk = K / BK;
    for (int kt = 0; kt < nk; kt++) {
        // issue global loads for next tile (hidden under compute)
        if (kt + 1 < nk) {
            const float* Ap = Ag + (kt + 1) * BK;
            const float* Wp = Wg + (kt + 1) * BK;
            ra[0] = *(const float4*)(Ap);
            ra[1] = *(const float4*)(Ap + (size_t)64 * K);
            #pragma unroll
            for (int i = 0; i < 4; i++) rb[i] = *(const float4*)(Wp + (size_t)(64*i) * K);
        }

        const float* as = As + (kt & 1) * ASTG;
        const float* ws = Ws + (kt & 1) * BSTG;
        #pragma unroll
        for (int kh = 0; kh < 2; kh++) {        // kk = 0, 8
            uint32_t af[4][4], bf[8][2];
            #pragma unroll
            for (int mt = 0; mt < 4; mt++) {
                int o0 = aof[2*kh]     + mt*256;
                int o1 = aof[2*kh + 1] + mt*256;
                af[mt][0] = __float_as_uint(as[o0]);
                af[mt][1] = __float_as_uint(as[o0 + 128]);
                af[mt][2] = __float_as_uint(as[o1]);
                af[mt][3] = __float_as_uint(as[o1 + 128]);
            }
            #pragma unroll
            for (int nt = 0; nt < 8; nt++) {
                bf[nt][0] = __float_as_uint(ws[bof[2*kh]     + nt*128]);
                bf[nt][1] = __float_as_uint(ws[bof[2*kh + 1] + nt*128]);
            }
            #pragma unroll
            for (int mt = 0; mt < 4; mt++)
                #pragma unroll
                for (int nt = 0; nt < 8; nt++)
                    mma_tf32(acc[mt][nt], af[mt], bf[nt][0], bf[nt][1]);
        }

        // fill the other stage for next iteration
        if (kt + 1 < nk) {
            float* as2 = As + ((kt + 1) & 1) * ASTG;
            float* ws2 = Ws + ((kt + 1) & 1) * BSTG;
            *(float4*)&as2[sA0]        = cvt4(ra[0]);
            *(float4*)&as2[sA0 + 1024] = cvt4(ra[1]);
            #pragma unroll
            for (int i = 0; i < 4; i++) *(float4*)&ws2[sB0 + i*1024] = cvt4(rb[i]);
        }
        __syncthreads();
    }

    // epilogue: float2 stores
    #pragma unroll
    for (int mt = 0; mt < 4; mt++) {
        int r = bM + wm*64 + mt*16 + g;
        #pragma unroll
        for (int nt = 0; nt < 8; nt++) {
            int c = bN + wn*64 + nt*8 + t*2;
            float2 v0 = make_float2(acc[mt][nt][0], acc[mt][nt][1]);
            float2 v1 = make_float2(acc[mt][nt][2], acc[mt][nt][3]);
            *(float2*)&C[(size_t)r * N + c]       = v0;
            *(float2*)&C[(size_t)(r + 8) * N + c] = v1;
        }
    }
}

// ============================================================
// RoPE (in place on [MROWS, D] viewed as [.., H, HD])
// ============================================================
__global__ void rope_kernel(float* __restrict__ P,
                            const float* __restrict__ cosT,
                            const float* __restrict__ sinT)
{
    int idx = blockIdx.x * blockDim.x + threadIdx.x;   // one thread per (row, h, hd<64)
    int hd  = idx & 63;
    int h   = (idx >> 6) & (Hh - 1);
    int row = idx >> 10;
    int s   = row & (Ss - 1);
    size_t base = (size_t)row * Dd + h * HDd;
    float q1 = P[base + hd], q2 = P[base + hd + 64];
    float c1 = cosT[s*HDd + hd],      s1 = sinT[s*HDd + hd];
    float c2 = cosT[s*HDd + hd + 64], s2 = sinT[s*HDd + hd + 64];
    P[base + hd]      = q1 * c1 - q2 * s1;
    P[base + hd + 64] = q2 * c2 + q1 * s2;
}

// ============================================================
// Flash attention: 64-query tile per block, 64-key tiles, causal.
// 4 warps, each owns 16 query rows. tf32 mma for QK^T and PV.
// (unchanged from R1 — optimize next round)
// ============================================================
#define QT 64
#define KT 64
#define QPAD 132
#define PPAD 68
#define ATTN_SMEM ((QT*QPAD + 2*KT*QPAD + QT*PPAD) * 4)   // 118784 B

__global__ __launch_bounds__(128) void attn_kernel()
{
    extern __shared__ float sm[];
    float* Qs = sm;                    // [QT][QPAD]
    float* Ks = Qs + QT*QPAD;          // [KT][QPAD]
    float* Vs = Ks + KT*QPAD;          // [KT][QPAD]
    float* Ps = Vs + KT*QPAD;          // [QT][PPAD]

    const int tid  = threadIdx.x;
    const int lane = tid & 31, warp = tid >> 5;
    const int g = lane >> 2, t = lane & 3;
    const int qtile = blockIdx.x;
    const int bh = blockIdx.y;
    const int b  = bh >> 4, h = bh & 15;
    const int q0 = qtile * QT;

    const size_t qgbase = (size_t)(b*Ss + q0) * Dd + h * HDd;
    #pragma unroll
    for (int i = 0; i < 16; i++) {
        int idx = tid + i * 128;
        int r = idx >> 5, c4 = (idx & 31) << 2;
        float4 v = *(const float4*)&g_Q[qgbase + (size_t)r*Dd + c4];
        Qs[r*QPAD + c4+0] = to_tf32f(v.x);
        Qs[r*QPAD + c4+1] = to_tf32f(v.y);
        Qs[r*QPAD + c4+2] = to_tf32f(v.z);
        Qs[r*QPAD + c4+3] = to_tf32f(v.w);
    }

    float accO[16][4];
    #pragma unroll
    for (int nt = 0; nt < 16; nt++)
        #pragma unroll
        for (int e = 0; e < 4; e++) accO[nt][e] = 0.f;
    float m0 = -INFINITY, m1 = -INFINITY, l0 = 0.f, l1 = 0.f;

    const int row0 = q0 + warp*16 + g;
    const int row1 = row0 + 8;

    for (int j = 0; j <= q0; j += KT) {
        __syncthreads();
        #pragma unroll
        for (int i = 0; i < 16; i++) {
            int idx = tid + i * 128;
            int r = idx >> 5, c4 = (idx & 31) << 2;
            size_t gb = (size_t)(b*Ss + j + r) * Dd + h * HDd + c4;
            float4 vk = *(const float4*)&g_K[gb];
            Ks[r*QPAD + c4+0] = to_tf32f(vk.x);
            Ks[r*QPAD + c4+1] = to_tf32f(vk.y);
            Ks[r*QPAD + c4+2] = to_tf32f(vk.z);
            Ks[r*QPAD + c4+3] = to_tf32f(vk.w);
            float4 vv = *(const float4*)&g_V[gb];
            Vs[r*QPAD + c4+0] = to_tf32f(vv.x);
            Vs[r*QPAD + c4+1] = to_tf32f(vv.y);
            Vs[r*QPAD + c4+2] = to_tf32f(vv.z);
            Vs[r*QPAD + c4+3] = to_tf32f(vv.w);
        }
        __syncthreads();

        float sc[8][4];
        #pragma unroll
        for (int nt = 0; nt < 8; nt++)
            #pragma unroll
            for (int e = 0; e < 4; e++) sc[nt][e] = 0.f;

        #pragma unroll
        for (int kk = 0; kk < HDd; kk += 8) {
            uint32_t a[4];
            int r = warp*16 + g;
            a[0] = __float_as_uint(Qs[r*QPAD     + kk + t]);
            a[1] = __float_as_uint(Qs[(r+8)*QPAD + kk + t]);
            a[2] = __float_as_uint(Qs[r*QPAD     + kk + t + 4]);
            a[3] = __float_as_uint(Qs[(r+8)*QPAD + kk + t + 4]);
            #pragma unroll
            for (int nt = 0; nt < 8; nt++) {
                int nr = nt*8 + g;
                uint32_t b0 = __float_as_uint(Ks[nr*QPAD + kk + t]);
                uint32_t b1 = __float_as_uint(Ks[nr*QPAD + kk + t + 4]);
                mma_tf32(sc[nt], a, b0, b1);
            }
        }

        const bool diag = (j == q0);
        #pragma unroll
        for (int nt = 0; nt < 8; nt++) {
            int col = j + nt*8 + t*2;
            sc[nt][0] *= ATTN_SCALE; sc[nt][1] *= ATTN_SCALE;
            sc[nt][2] *= ATTN_SCALE; sc[nt][3] *= ATTN_SCALE;
            if (diag) {
                if (col     > row0) sc[nt][0] = -INFINITY;
                if (col + 1 > row0) sc[nt][1] = -INFINITY;
                if (col     > row1) sc[nt][2] = -INFINITY;
                if (col + 1 > row1) sc[nt][3] = -INFINITY;
            }
        }

        float rm0 = -INFINITY, rm1 = -INFINITY;
        #pragma unroll
        for (int nt = 0; nt < 8; nt++) {
            rm0 = fmaxf(rm0, fmaxf(sc[nt][0], sc[nt][1]));
            rm1 = fmaxf(rm1, fmaxf(sc[nt][2], sc[nt][3]));
        }
        rm0 = fmaxf(rm0, __shfl_xor_sync(0xffffffffu, rm0, 1));
        rm0 = fmaxf(rm0, __shfl_xor_sync(0xffffffffu, rm0, 2));
        rm1 = fmaxf(rm1, __shfl_xor_sync(0xffffffffu, rm1, 1));
        rm1 = fmaxf(rm1, __shfl_xor_sync(0xffffffffu, rm1, 2));

        float m0n = fmaxf(m0, rm0), m1n = fmaxf(m1, rm1);
        float al0 = __expf(m0 - m0n), al1 = __expf(m1 - m1n);
        float sum0 = 0.f, sum1 = 0.f;
        int pr0 = warp*16 + g, pr1 = pr0 + 8;
        #pragma unroll
        for (int nt = 0; nt < 8; nt++) {
            int cb = nt*8 + t*2;
            float p0 = __expf(sc[nt][0] - m0n);
            float p1 = __expf(sc[nt][1] - m0n);
            float p2 = __expf(sc[nt][2] - m1n);
            float p3 = __expf(sc[nt][3] - m1n);
            sum0 += p0 + p1; sum1 += p2 + p3;
            Ps[pr0*PPAD + cb]     = to_tf32f(p0);
            Ps[pr0*PPAD + cb + 1] = to_tf32f(p1);
            Ps[pr1*PPAD + cb]     = to_tf32f(p2);
            Ps[pr1*PPAD + cb + 1] = to_tf32f(p3);
        }
        sum0 += __shfl_xor_sync(0xffffffffu, sum0, 1);
        sum0 += __shfl_xor_sync(0xffffffffu, sum0, 2);
        sum1 += __shfl_xor_sync(0xffffffffu, sum1, 1);
        sum1 += __shfl_xor_sync(0xffffffffu, sum1, 2);
        l0 = l0 * al0 + sum0;
        l1 = l1 * al1 + sum1;
        m0 = m0n; m1 = m1n;
        #pragma unroll
        for (int nt = 0; nt < 16; nt++) {
            accO[nt][0] *= al0; accO[nt][1] *= al0;
            accO[nt][2] *= al1; accO[nt][3] *= al1;
        }
        __syncwarp();

        #pragma unroll
        for (int kk = 0; kk < KT; kk += 8) {
            uint32_t a[4];
            a[0] = __float_as_uint(Ps[pr0*PPAD + kk + t]);
            a[1] = __float_as_uint(Ps[pr1*PPAD + kk + t]);
            a[2] = __float_as_uint(Ps[pr0*PPAD + kk + t + 4]);
            a[3] = __float_as_uint(Ps[pr1*PPAD + kk + t + 4]);
            #pragma unroll
            for (int nt = 0; nt < 16; nt++) {
                uint32_t b0 = __float_as_uint(Vs[(kk + t)*QPAD     + nt*8 + g]);
                uint32_t b1 = __float_as_uint(Vs[(kk + t + 4)*QPAD + nt*8 + g]);
                mma_tf32(accO[nt], a, b0, b1);
            }
        }
    }

    float inv0 = 1.f / l0, inv1 = 1.f / l1;
    size_t obase = (size_t)(b*Ss + q0 + warp*16 + g) * Dd + h * HDd;
    #pragma unroll
    for (int nt = 0; nt < 16; nt++) {
        int cb = nt*8 + t*2;
        g_A[obase + cb]              = accO[nt][0] * inv0;
        g_A[obase + cb + 1]          = accO[nt][1] * inv0;
        g_A[obase + (size_t)8*Dd + cb]     = accO[nt][2] * inv1;
        g_A[obase + (size_t)8*Dd + cb + 1] = accO[nt][3] * inv1;
    }
}

// ============================================================
extern "C" void kernel_launch(void* const* d_in, const int* in_sizes, int n_in,
                              void* d_out, int out_size)
{
    (void)in_sizes; (void)n_in; (void)out_size;
    const float* x    = (const float*)d_in[0];
    // d_in[1] = mask (unused — causal implemented directly)
    const float* cosT = (const float*)d_in[2];
    const float* sinT = (const float*)d_in[3];
    const float* Wq   = (const float*)d_in[4];
    const float* Wk   = (const float*)d_in[5];
    const float* Wv   = (const float*)d_in[6];
    const float* Wo   = (const float*)d_in[7];
    float* out = (float*)d_out;

    float *qp, *kp, *vp, *ap;
    cudaGetSymbolAddress((void**)&qp, g_Q);
    cudaGetSymbolAddress((void**)&kp, g_K);
    cudaGetSymbolAddress((void**)&vp, g_V);
    cudaGetSymbolAddress((void**)&ap, g_A);

    dim3 gg(Dd / BN, MROWS / BM);   // (8, 32)
    gemm_nt<<<gg, 256>>>(x, Wq, qp, MROWS, Dd, Dd);
    gemm_nt<<<gg, 256>>>(x, Wk, kp, MROWS, Dd, Dd);
    gemm_nt<<<gg, 256>>>(x, Wv, vp, MROWS, Dd, Dd);

    int nrope = MROWS * Hh * 64;
    rope_kernel<<<nrope / 256, 256>>>(qp, cosT, sinT);
    rope_kernel<<<nrope / 256, 256>>>(kp, cosT, sinT);

    cudaFuncSetAttribute(attn_kernel, cudaFuncAttributeMaxDynamicSharedMemorySize, ATTN_SMEM);
    attn_kernel<<<dim3(Ss / QT, Bb * Hh), 128, ATTN_SMEM>>>();

    gemm_nt<<<gg, 256>>>(ap, Wo, out, MROWS, Dd, Dd);
}

// round 6
// speedup vs baseline: 1.4196x; 1.0109x over previous
#include <cuda_runtime.h>
#include <cuda_bf16.h>
#include <cstdint>

// Problem constants
#define Bb 2
#define Ss 2048
#define Dd 2048
#define Hh 16
#define HDd 128
#define MROWS (Bb*Ss)              // 4096
#define ATTN_SCALE 0.08838834764831845f  // 1/sqrt(128)

// Scratch (static device globals: allocation-free rule)
__device__ float g_Q[(size_t)MROWS*Dd];
__device__ float g_K[(size_t)MROWS*Dd];
__device__ float g_V[(size_t)MROWS*Dd];
__device__ float g_A[(size_t)MROWS*Dd];

// ------------------------------------------------------------------
// helpers
// ------------------------------------------------------------------
__device__ __forceinline__ float to_tf32f(float x){
    uint32_t u; asm("cvt.rna.tf32.f32 %0, %1;" : "=r"(u) : "f"(x));
    return __uint_as_float(u);
}
__device__ __forceinline__ uint32_t frag_tf32(float x){
    uint32_t u; asm("cvt.rna.tf32.f32 %0, %1;" : "=r"(u) : "f"(x));
    return u;
}
__device__ __forceinline__ uint32_t smem_u32(const void* p){
    uint32_t a;
    asm("{ .reg .u64 t; cvta.to.shared.u64 t, %1; cvt.u32.u64 %0, t; }"
        : "=r"(a) : "l"(p));
    return a;
}
__device__ __forceinline__ void mma_tf32(float c[4], const uint32_t a[4],
                                         uint32_t b0, uint32_t b1){
    asm volatile("mma.sync.aligned.m16n8k8.row.col.f32.tf32.tf32.f32 "
        "{%0,%1,%2,%3}, {%4,%5,%6,%7}, {%8,%9}, {%0,%1,%2,%3};\n"
        : "+f"(c[0]), "+f"(c[1]), "+f"(c[2]), "+f"(c[3])
        : "r"(a[0]), "r"(a[1]), "r"(a[2]), "r"(a[3]), "r"(b0), "r"(b1));
}

#define CP_ASYNC16(sa, ga) \
    asm volatile("cp.async.cg.shared.global [%0], [%1], 16;" :: "r"(sa), "l"(ga))
#define CP_COMMIT() asm volatile("cp.async.commit_group;" ::: "memory")
#define CP_WAIT(n)  asm volatile("cp.async.wait_group %0;" :: "n"(n) : "memory")

// ------------------------------------------------------------------
// GEMM: C[M,N] = A[M,K] * W[N,K]^T    (legacy tf32 mma, cp.async pipeline)
// 128x256 block, 8 warps (2x4) of 64x64, BK=16, 4 stages.
// SMEM rows padded to 20 words: fragment bank = (20g + t) mod 32, conflict-free.
// A/W are raw fp32 in global; tf32 RNA conversion happens in registers.
// round_out != 0 -> epilogue rounds C to tf32 (RNA).
// ------------------------------------------------------------------
#define GM 4096
#define GN 2048
#define GK 2048
#define BK 16
#define SSTR 20                        // words per smem row
#define A_WORDS (128*SSTR)             // 2560
#define B_WORDS (256*SSTR)             // 5120
#define STG_WORDS (A_WORDS + B_WORDS)  // 7680
#define G_STAGES 4
#define G_SMEM (G_STAGES*STG_WORDS*4)  // 122880 B
#define G_NK (GK/BK)                   // 128

__global__ __launch_bounds__(256, 1) void gemm_ca(const float* __restrict__ A,
                                                  const float* __restrict__ W,
                                                  float* __restrict__ C,
                                                  int round_out)
{
    extern __shared__ float smem[];
    const int tid  = threadIdx.x;
    const int lane = tid & 31, warp = tid >> 5;
    const int wm = warp >> 2, wn = warp & 3;      // 2 x 4 warp grid (64x64 tiles)
    const int g = lane >> 2, t = lane & 3;
    const int bM = blockIdx.y * 128, bN = blockIdx.x * 256;

    // fill pattern: thread -> row = tid>>2 (+64 steps), col4 = (tid&3)*4
    const int frow = tid >> 2, fcol = (tid & 3) << 2;
    const float* Ag = A + (size_t)(bM + frow) * GK + fcol;
    const float* Wg = W + (size_t)(bN + frow) * GK + fcol;
    const uint32_t smem_base = smem_u32(smem);
    const uint32_t fillA = smem_base + (uint32_t)(frow * SSTR + fcol) * 4u;
    const uint32_t fillB = smem_base + (uint32_t)(A_WORDS + frow * SSTR + fcol) * 4u;

    // fragment base word offsets (within stage)
    const int aro = (wm*64 + g) * SSTR;         // + mt*16*SSTR, +8*SSTR, +kk+t
    const int bro = (wn*64 + g) * SSTR;         // + nt*8*SSTR, +kk+t

    float acc[4][8][4];
    #pragma unroll
    for (int mt = 0; mt < 4; mt++)
        #pragma unroll
        for (int nt = 0; nt < 8; nt++)
            #pragma unroll
            for (int e = 0; e < 4; e++) acc[mt][nt][e] = 0.f;

    // prologue: fill stages 0..2
    #pragma unroll
    for (int s = 0; s < G_STAGES - 1; s++) {
        uint32_t sa = fillA + s * (STG_WORDS * 4);
        uint32_t sw = fillB + s * (STG_WORDS * 4);
        const float* ap = Ag + s * BK;
        const float* wp = Wg + s * BK;
        CP_ASYNC16(sa, ap);
        CP_ASYNC16(sa + 64*SSTR*4, ap + (size_t)64 * GK);
        #pragma unroll
        for (int i = 0; i < 4; i++)
            CP_ASYNC16(sw + i*64*SSTR*4, wp + (size_t)(64*i) * GK);
        CP_COMMIT();
    }

    for (int kt = 0; kt < G_NK; kt++) {
        CP_WAIT(2);
        __syncthreads();

        // prefetch tile kt+3 into slot (kt+3)%4 (its previous contents, tile
        // kt-1, were consumed before the barrier above)
        {
            const int pf = kt + G_STAGES - 1;
            if (pf < G_NK) {
                const int sp = pf & (G_STAGES - 1);
                uint32_t sa = fillA + sp * (STG_WORDS * 4);
                uint32_t sw = fillB + sp * (STG_WORDS * 4);
                const float* ap = Ag + pf * BK;
                const float* wp = Wg + pf * BK;
                CP_ASYNC16(sa, ap);
                CP_ASYNC16(sa + 64*SSTR*4, ap + (size_t)64 * GK);
                #pragma unroll
                for (int i = 0; i < 4; i++)
                    CP_ASYNC16(sw + i*64*SSTR*4, wp + (size_t)(64*i) * GK);
            }
            CP_COMMIT();   // uniform group accounting (empty in tail)
        }

        const float* as = smem + (kt & (G_STAGES - 1)) * STG_WORDS;
        const float* ws = as + A_WORDS;
        #pragma unroll
        for (int kh = 0; kh < 2; kh++) {        // kk = 0, 8
            const int kk = kh * 8;
            uint32_t af[4][4], bf[8][2];
            #pragma unroll
            for (int mt = 0; mt < 4; mt++) {
                int o = aro + mt*16*SSTR + kk + t;
                af[mt][0] = frag_tf32(as[o]);
                af[mt][1] = frag_tf32(as[o + 8*SSTR]);
                af[mt][2] = frag_tf32(as[o + 4]);
                af[mt][3] = frag_tf32(as[o + 8*SSTR + 4]);
            }
            #pragma unroll
            for (int nt = 0; nt < 8; nt++) {
                int o = bro + nt*8*SSTR + kk + t;
                bf[nt][0] = frag_tf32(ws[o]);
                bf[nt][1] = frag_tf32(ws[o + 4]);
            }
            #pragma unroll
            for (int mt = 0; mt < 4; mt++)
                #pragma unroll
                for (int nt = 0; nt < 8; nt++)
                    mma_tf32(acc[mt][nt], af[mt], bf[nt][0], bf[nt][1]);
        }
        __syncthreads();
    }

    // epilogue
    #pragma unroll
    for (int mt = 0; mt < 4; mt++) {
        int r = bM + wm*64 + mt*16 + g;
        #pragma unroll
        for (int nt = 0; nt < 8; nt++) {
            int c = bN + wn*64 + nt*8 + t*2;
            float v0 = acc[mt][nt][0], v1 = acc[mt][nt][1];
            float v2 = acc[mt][nt][2], v3 = acc[mt][nt][3];
            if (round_out) {
                v0 = to_tf32f(v0); v1 = to_tf32f(v1);
                v2 = to_tf32f(v2); v3 = to_tf32f(v3);
            }
            *(float2*)&C[(size_t)r * GN + c]       = make_float2(v0, v1);
            *(float2*)&C[(size_t)(r + 8) * GN + c] = make_float2(v2, v3);
        }
    }
}

// ------------------------------------------------------------------
// RoPE (in place; output rounded to tf32 so attention can load raw)
// ------------------------------------------------------------------
__global__ void rope_kernel(float* __restrict__ P,
                            const float* __restrict__ cosT,
                            const float* __restrict__ sinT)
{
    int idx = blockIdx.x * blockDim.x + threadIdx.x;
    int hd  = idx & 63;
    int h   = (idx >> 6) & (Hh - 1);
    int row = idx >> 10;
    int s   = row & (Ss - 1);
    size_t base = (size_t)row * Dd + h * HDd;
    float q1 = P[base + hd], q2 = P[base + hd + 64];
    float c1 = cosT[s*HDd + hd],      s1 = sinT[s*HDd + hd];
    float c2 = cosT[s*HDd + hd + 64], s2 = sinT[s*HDd + hd + 64];
    P[base + hd]      = to_tf32f(q1 * c1 - q2 * s1);
    P[base + hd + 64] = to_tf32f(q2 * c2 + q1 * s2);
}

// ------------------------------------------------------------------
// Flash attention, 64-query tiles, causal. 4 warps x 16 query rows.
// K/V double-buffered via cp.async (Q/K/V pre-rounded tf32 in global).
// K stride 132 (bank 4g+t, conflict-free); V stride 136 (bank 8t+8n+g,
// conflict-free -- fixes the 4-way conflict of the 132-stride layout).
// ------------------------------------------------------------------
#define QT 64
#define KSTR 132
#define VSTR 136
#define PSTR 68
#define QW (QT*KSTR)        // 8448
#define KW (QT*KSTR)        // 8448 per buffer
#define VW (QT*VSTR)        // 8704 per buffer
#define PW (QT*PSTR)        // 4352
#define ATTN_SMEM ((QW + 2*KW + 2*VW + PW) * 4)   // 188416 B

__global__ __launch_bounds__(128) void attn_kernel()
{
    extern __shared__ float sm[];
    float* Qs = sm;                     // [64][132]
    float* K0 = Qs + QW;
    float* K1 = K0 + KW;
    float* V0 = K1 + KW;                // [64][136]
    float* V1 = V0 + VW;
    float* Ps = V1 + VW;                // [64][68]

    const int tid  = threadIdx.x;
    const int lane = tid & 31, warp = tid >> 5;
    const int g = lane >> 2, t = lane & 3;
    const int qtile = blockIdx.x;
    const int bh = blockIdx.y;
    const int b  = bh >> 4, h = bh & 15;
    const int q0 = qtile * QT;

    const uint32_t k0a = smem_u32(K0), k1a = smem_u32(K1);
    const uint32_t v0a = smem_u32(V0), v1a = smem_u32(V1);

    // per-thread fill pattern: 16 chunks of 16B for K, 16 for V
    const size_t kvcol = h * HDd;

    // prologue: cp.async tile 0 into buffer 0
    {
        #pragma unroll
        for (int i = 0; i < 16; i++) {
            int idx = tid + i * 128;
            int r = idx >> 5, c4 = (idx & 31) << 2;
            size_t gsrc = (size_t)(b*Ss + r) * Dd + kvcol + c4;
            CP_ASYNC16(k0a + (uint32_t)(r*KSTR + c4)*4u, g_K + gsrc);
            CP_ASYNC16(v0a + (uint32_t)(r*VSTR + c4)*4u, g_V + gsrc);
        }
        CP_COMMIT();
    }

    // Q tile (pre-rounded, plain loads)
    const size_t qgbase = (size_t)(b*Ss + q0) * Dd + kvcol;
    #pragma unroll
    for (int i = 0; i < 16; i++) {
        int idx = tid + i * 128;
        int r = idx >> 5, c4 = (idx & 31) << 2;
        float4 v = *(const float4*)&g_Q[qgbase + (size_t)r*Dd + c4];
        *(float4*)&Qs[r*KSTR + c4] = v;
    }

    float accO[16][4];
    #pragma unroll
    for (int nt = 0; nt < 16; nt++)
        #pragma unroll
        for (int e = 0; e < 4; e++) accO[nt][e] = 0.f;
    float m0 = -INFINITY, m1 = -INFINITY, l0 = 0.f, l1 = 0.f;

    const int row0 = q0 + warp*16 + g;
    const int row1 = row0 + 8;
    const int nj = qtile + 1;

    for (int jt = 0; jt < nj; jt++) {
        CP_WAIT(0);
        __syncthreads();

        // prefetch next KV tile into the other buffer (safe: its previous
        // contents were consumed in iteration jt-1, all warps past barrier)
        if (jt + 1 < nj) {
            const uint32_t ka = ((jt + 1) & 1) ? k1a : k0a;
            const uint32_t va = ((jt + 1) & 1) ? v1a : v0a;
            const int jrow = (jt + 1) * QT;
            #pragma unroll
            for (int i = 0; i < 16; i++) {
                int idx = tid + i * 128;
                int r = idx >> 5, c4 = (idx & 31) << 2;
                size_t gsrc = (size_t)(b*Ss + jrow + r) * Dd + kvcol + c4;
                CP_ASYNC16(ka + (uint32_t)(r*KSTR + c4)*4u, g_K + gsrc);
                CP_ASYNC16(va + (uint32_t)(r*VSTR + c4)*4u, g_V + gsrc);
            }
            CP_COMMIT();
        }

        const float* Ks = (jt & 1) ? K1 : K0;
        const float* Vs = (jt & 1) ? V1 : V0;
        const int j = jt * QT;

        // ---- scores = Q K^T (warp: 16 x 64) ----
        float sc[8][4];
        #pragma unroll
        for (int nt = 0; nt < 8; nt++)
            #pragma unroll
            for (int e = 0; e < 4; e++) sc[nt][e] = 0.f;

        const int qr = warp*16 + g;
        #pragma unroll
        for (int kk = 0; kk < HDd; kk += 8) {
            uint32_t a[4];
            a[0] = __float_as_uint(Qs[qr*KSTR     + kk + t]);
            a[1] = __float_as_uint(Qs[(qr+8)*KSTR + kk + t]);
            a[2] = __float_as_uint(Qs[qr*KSTR     + kk + t + 4]);
            a[3] = __float_as_uint(Qs[(qr+8)*KSTR + kk + t + 4]);
            #pragma unroll
            for (int nt = 0; nt < 8; nt++) {
                int nr = nt*8 + g;
                uint32_t b0 = __float_as_uint(Ks[nr*KSTR + kk + t]);
                uint32_t b1 = __float_as_uint(Ks[nr*KSTR + kk + t + 4]);
                mma_tf32(sc[nt], a, b0, b1);
            }
        }

        // ---- scale + causal mask (diagonal tile only) ----
        const bool diag = (jt == nj - 1);
        #pragma unroll
        for (int nt = 0; nt < 8; nt++) {
            int col = j + nt*8 + t*2;
            sc[nt][0] *= ATTN_SCALE; sc[nt][1] *= ATTN_SCALE;
            sc[nt][2] *= ATTN_SCALE; sc[nt][3] *= ATTN_SCALE;
            if (diag) {
                if (col     > row0) sc[nt][0] = -INFINITY;
                if (col + 1 > row0) sc[nt][1] = -INFINITY;
                if (col     > row1) sc[nt][2] = -INFINITY;
                if (col + 1 > row1) sc[nt][3] = -INFINITY;
            }
        }

        // ---- online softmax ----
        float rm0 = -INFINITY, rm1 = -INFINITY;
        #pragma unroll
        for (int nt = 0; nt < 8; nt++) {
            rm0 = fmaxf(rm0, fmaxf(sc[nt][0], sc[nt][1]));
            rm1 = fmaxf(rm1, fmaxf(sc[nt][2], sc[nt][3]));
        }
        rm0 = fmaxf(rm0, __shfl_xor_sync(0xffffffffu, rm0, 1));
        rm0 = fmaxf(rm0, __shfl_xor_sync(0xffffffffu, rm0, 2));
        rm1 = fmaxf(rm1, __shfl_xor_sync(0xffffffffu, rm1, 1));
        rm1 = fmaxf(rm1, __shfl_xor_sync(0xffffffffu, rm1, 2));

        float m0n = fmaxf(m0, rm0), m1n = fmaxf(m1, rm1);
        float al0 = __expf(m0 - m0n), al1 = __expf(m1 - m1n);
        float sum0 = 0.f, sum1 = 0.f;
        const int pr0 = warp*16 + g, pr1 = pr0 + 8;
        #pragma unroll
        for (int nt = 0; nt < 8; nt++) {
            int cb = nt*8 + t*2;
            float p0 = __expf(sc[nt][0] - m0n);
            float p1 = __expf(sc[nt][1] - m0n);
            float p2 = __expf(sc[nt][2] - m1n);
            float p3 = __expf(sc[nt][3] - m1n);
            sum0 += p0 + p1; sum1 += p2 + p3;
            Ps[pr0*PSTR + cb]     = to_tf32f(p0);
            Ps[pr0*PSTR + cb + 1] = to_tf32f(p1);
            Ps[pr1*PSTR + cb]     = to_tf32f(p2);
            Ps[pr1*PSTR + cb + 1] = to_tf32f(p3);
        }
        sum0 += __shfl_xor_sync(0xffffffffu, sum0, 1);
        sum0 += __shfl_xor_sync(0xffffffffu, sum0, 2);
        sum1 += __shfl_xor_sync(0xffffffffu, sum1, 1);
        sum1 += __shfl_xor_sync(0xffffffffu, sum1, 2);
        l0 = l0 * al0 + sum0;
        l1 = l1 * al1 + sum1;
        m0 = m0n; m1 = m1n;
        #pragma unroll
        for (int nt = 0; nt < 16; nt++) {
            accO[nt][0] *= al0; accO[nt][1] *= al0;
            accO[nt][2] *= al1; accO[nt][3] *= al1;
        }
        __syncwarp();   // Ps rows are per-warp: write->read ordering

        // ---- O += P V (warp: 16 x 128), V stride 136 => conflict-free ----
        #pragma unroll
        for (int kk = 0; kk < QT; kk += 8) {
            uint32_t a[4];
            a[0] = __float_as_uint(Ps[pr0*PSTR + kk + t]);
            a[1] = __float_as_uint(Ps[pr1*PSTR + kk + t]);
            a[2] = __float_as_uint(Ps[pr0*PSTR + kk + t + 4]);
            a[3] = __float_as_uint(Ps[pr1*PSTR + kk + t + 4]);
            #pragma unroll
            for (int nt = 0; nt < 16; nt++) {
                uint32_t b0 = __float_as_uint(Vs[(kk + t)*VSTR     + nt*8 + g]);
                uint32_t b1 = __float_as_uint(Vs[(kk + t + 4)*VSTR + nt*8 + g]);
                mma_tf32(accO[nt], a, b0, b1);
            }
        }
    }

    // ---- epilogue: normalize + round (feeds Wo GEMM) ----
    float inv0 = 1.f / l0, inv1 = 1.f / l1;
    size_t obase = (size_t)(b*Ss + q0 + warp*16 + g) * Dd + h * HDd;
    #pragma unroll
    for (int nt = 0; nt < 16; nt++) {
        int cb = nt*8 + t*2;
        g_A[obase + cb]                    = to_tf32f(accO[nt][0] * inv0);
        g_A[obase + cb + 1]                = to_tf32f(accO[nt][1] * inv0);
        g_A[obase + (size_t)8*Dd + cb]     = to_tf32f(accO[nt][2] * inv1);
        g_A[obase + (size_t)8*Dd + cb + 1] = to_tf32f(accO[nt][3] * inv1);
    }
}

// ============================================================
extern "C" void kernel_launch(void* const* d_in, const int* in_sizes, int n_in,
                              void* d_out, int out_size)
{
    (void)in_sizes; (void)n_in; (void)out_size;
    const float* x    = (const float*)d_in[0];
    // d_in[1] = mask (unused -- causal implemented directly)
    const float* cosT = (const float*)d_in[2];
    const float* sinT = (const float*)d_in[3];
    const float* Wq   = (const float*)d_in[4];
    const float* Wk   = (const float*)d_in[5];
    const float* Wv   = (const float*)d_in[6];
    const float* Wo   = (const float*)d_in[7];
    float* out = (float*)d_out;

    float *qp, *kp, *vp, *ap;
    cudaGetSymbolAddress((void**)&qp, g_Q);
    cudaGetSymbolAddress((void**)&kp, g_K);
    cudaGetSymbolAddress((void**)&vp, g_V);
    cudaGetSymbolAddress((void**)&ap, g_A);

    cudaFuncSetAttribute(gemm_ca, cudaFuncAttributeMaxDynamicSharedMemorySize, G_SMEM);
    dim3 gg(GN / 256, GM / 128);   // (8, 32)
    // Q,K,V projections: epilogue rounds to tf32 (attention loads them raw)
    gemm_ca<<<gg, 256, G_SMEM>>>(x, Wq, qp, 1);
    gemm_ca<<<gg, 256, G_SMEM>>>(x, Wk, kp, 1);
    gemm_ca<<<gg, 256, G_SMEM>>>(x, Wv, vp, 1);

    int nrope = MROWS * Hh * 64;
    rope_kernel<<<nrope / 256, 256>>>(qp, cosT, sinT);
    rope_kernel<<<nrope / 256, 256>>>(kp, cosT, sinT);

    cudaFuncSetAttribute(attn_kernel, cudaFuncAttributeMaxDynamicSharedMemorySize, ATTN_SMEM);
    attn_kernel<<<dim3(Ss / QT, Bb * Hh), 128, ATTN_SMEM>>>();

    // output projection: plain fp32 epilogue
    gemm_ca<<<gg, 256, G_SMEM>>>(ap, Wo, out, 0);
}

// round 9
// speedup vs baseline: 2.9055x; 2.0467x over previous
#include <cuda_runtime.h>
#include <cuda_fp16.h>
#include <cstdint>

// Problem constants
#define Bb 2
#define Ss 2048
#define Dd 2048
#define Hh 16
#define HDd 128
#define MROWS (Bb*Ss)              // 4096
#define ATTN_SCALE 0.08838834764831845f  // 1/sqrt(128)

// Scratch (static device globals: allocation-free rule)
__device__ __half g_Xh[(size_t)MROWS*Dd];
__device__ __half g_Wh[4][(size_t)Dd*Dd];
__device__ __half g_Qh[(size_t)MROWS*Dd];
__device__ __half g_Kh[(size_t)MROWS*Dd];
__device__ __half g_Vh[(size_t)MROWS*Dd];
__device__ __half g_Ah[(size_t)MROWS*Dd];

// ------------------------------------------------------------------
// helpers
// ------------------------------------------------------------------
__device__ __forceinline__ uint32_t pk2(float a, float b){
    __half2 h = __floats2half2_rn(a, b);   // .x = a (low half = lower k index)
    return *reinterpret_cast<uint32_t*>(&h);
}
__device__ __forceinline__ uint32_t smem_u32(const void* p){
    uint32_t a;
    asm("{ .reg .u64 t; cvta.to.shared.u64 t, %1; cvt.u32.u64 %0, t; }"
        : "=r"(a) : "l"(p));
    return a;
}
__device__ __forceinline__ void mma_f16(float c[4], const uint32_t a[4],
                                        uint32_t b0, uint32_t b1){
    asm volatile("mma.sync.aligned.m16n8k16.row.col.f32.f16.f16.f32 "
        "{%0,%1,%2,%3}, {%4,%5,%6,%7}, {%8,%9}, {%0,%1,%2,%3};\n"
        : "+f"(c[0]), "+f"(c[1]), "+f"(c[2]), "+f"(c[3])
        : "r"(a[0]), "r"(a[1]), "r"(a[2]), "r"(a[3]), "r"(b0), "r"(b1));
}
__device__ __forceinline__ void ldm_x2_t(uint32_t &r0, uint32_t &r1, uint32_t addr){
    asm volatile("ldmatrix.sync.aligned.m8n8.x2.trans.shared.b16 {%0,%1}, [%2];"
        : "=r"(r0), "=r"(r1) : "r"(addr));
}

#define CP_ASYNC16(sa, ga) \
    asm volatile("cp.async.cg.shared.global [%0], [%1], 16;" :: "r"(sa), "l"(ga))
#define CP_COMMIT() asm volatile("cp.async.commit_group;" ::: "memory")
#define CP_WAIT(n)  asm volatile("cp.async.wait_group %0;" :: "n"(n) : "memory")

// ------------------------------------------------------------------
// pack fp32 -> fp16
// ------------------------------------------------------------------
__global__ void pack_half(const float4* __restrict__ in, uint32_t* __restrict__ out,
                          int n4){
    int i = blockIdx.x * blockDim.x + threadIdx.x;
    if (i < n4) {
        float4 v = in[i];
        out[2*i]   = pk2(v.x, v.y);
        out[2*i+1] = pk2(v.z, v.w);
    }
}

// ------------------------------------------------------------------
// GEMM: C[M,N] = A[M,K] * W[N,K]^T   (fp16 m16n8k16, fp32 accum)
// 128x256 block, 8 warps (2x4) of 64x64, BK=32 halves, 4-stage cp.async.
// SMEM unit = half2 word (4B). Row = 16 words data + 4 pad (SSTR=20):
// fragment bank = (20g + t) mod 32 -> all 32 lanes distinct.
// outh != 0 -> write half2 to C; else write fp32.
// ------------------------------------------------------------------
#define GM 4096
#define GN 2048
#define GK 2048
#define BKH 32                          // halves per k-tile
#define SSTR 20                         // words per smem row
#define A_WORDS (128*SSTR)              // 2560
#define B_WORDS (256*SSTR)              // 5120
#define STG_WORDS (A_WORDS + B_WORDS)   // 7680
#define G_STAGES 4
#define G_SMEM (G_STAGES*STG_WORDS*4)   // 122880 B
#define G_NK (GK/BKH)                   // 64

__global__ __launch_bounds__(256, 1) void gemm_h(const __half* __restrict__ A,
                                                 const __half* __restrict__ W,
                                                 void* __restrict__ Cv,
                                                 int outh)
{
    extern __shared__ uint32_t smw[];
    const int tid  = threadIdx.x;
    const int lane = tid & 31, warp = tid >> 5;
    const int wm = warp >> 2, wn = warp & 3;      // 2 x 4 warp grid (64x64)
    const int g = lane >> 2, t = lane & 3;
    const int bM = blockIdx.y * 128, bN = blockIdx.x * 256;

    // fill pattern: chunk = 16B (8 halves). A: 512 chunks, B: 1024 chunks.
    // chunk id -> row = id>>2, c = id&3 (coalesced 64B per 4 threads).
    const int frow = tid >> 2, fc = tid & 3;
    const __half* Ag = A + (size_t)(bM + frow) * GK + fc * 8;
    const __half* Wg = W + (size_t)(bN + frow) * GK + fc * 8;
    const uint32_t smem_base = smem_u32(smw);
    const uint32_t fillA = smem_base + (uint32_t)(frow * SSTR + fc * 4) * 4u;
    const uint32_t fillB = smem_base + (uint32_t)(A_WORDS + frow * SSTR + fc * 4) * 4u;

    const int aro = (wm*64 + g) * SSTR;     // + mt*16*SSTR + ks*8 + t (+4, +8*SSTR)
    const int bro = (wn*64 + g) * SSTR;     // + nt*8*SSTR + ks*8 + t (+4)

    float acc[4][8][4];
    #pragma unroll
    for (int mt = 0; mt < 4; mt++)
        #pragma unroll
        for (int nt = 0; nt < 8; nt++)
            #pragma unroll
            for (int e = 0; e < 4; e++) acc[mt][nt][e] = 0.f;

    // prologue: fill stages 0..2
    #pragma unroll
    for (int s = 0; s < G_STAGES - 1; s++) {
        uint32_t sa = fillA + s * (STG_WORDS * 4);
        uint32_t sw = fillB + s * (STG_WORDS * 4);
        const __half* ap = Ag + s * BKH;
        const __half* wp = Wg + s * BKH;
        CP_ASYNC16(sa, ap);
        CP_ASYNC16(sa + 64*SSTR*4, ap + (size_t)64 * GK);
        #pragma unroll
        for (int i = 0; i < 4; i++)
            CP_ASYNC16(sw + i*64*SSTR*4, wp + (size_t)(64*i) * GK);
        CP_COMMIT();
    }

    for (int kt = 0; kt < G_NK; kt++) {
        CP_WAIT(2);
        __syncthreads();

        {   // prefetch tile kt+3 into slot (kt+3)%4
            const int pf = kt + G_STAGES - 1;
            if (pf < G_NK) {
                const int sp = pf & (G_STAGES - 1);
                uint32_t sa = fillA + sp * (STG_WORDS * 4);
                uint32_t sw = fillB + sp * (STG_WORDS * 4);
                const __half* ap = Ag + pf * BKH;
                const __half* wp = Wg + pf * BKH;
                CP_ASYNC16(sa, ap);
                CP_ASYNC16(sa + 64*SSTR*4, ap + (size_t)64 * GK);
                #pragma unroll
                for (int i = 0; i < 4; i++)
                    CP_ASYNC16(sw + i*64*SSTR*4, wp + (size_t)(64*i) * GK);
            }
            CP_COMMIT();
        }

        const uint32_t* as = smw + (kt & (G_STAGES - 1)) * STG_WORDS;
        const uint32_t* ws = as + A_WORDS;
        #pragma unroll
        for (int ks = 0; ks < 2; ks++) {        // k halves 0-15, 16-31
            const int kk2 = ks * 8;
            uint32_t af[4][4], bf[8][2];
            #pragma unroll
            for (int mt = 0; mt < 4; mt++) {
                int o = aro + mt*16*SSTR + kk2 + t;
                af[mt][0] = as[o];
                af[mt][1] = as[o + 8*SSTR];
                af[mt][2] = as[o + 4];
                af[mt][3] = as[o + 8*SSTR + 4];
            }
            #pragma unroll
            for (int nt = 0; nt < 8; nt++) {
                int o = bro + nt*8*SSTR + kk2 + t;
                bf[nt][0] = ws[o];
                bf[nt][1] = ws[o + 4];
            }
            #pragma unroll
            for (int mt = 0; mt < 4; mt++)
                #pragma unroll
                for (int nt = 0; nt < 8; nt++)
                    mma_f16(acc[mt][nt], af[mt], bf[nt][0], bf[nt][1]);
        }
        __syncthreads();
    }

    // epilogue
    if (outh) {
        uint32_t* Cw = (uint32_t*)Cv;   // half2 words, N/2 per row
        #pragma unroll
        for (int mt = 0; mt < 4; mt++) {
            int r = bM + wm*64 + mt*16 + g;
            #pragma unroll
            for (int nt = 0; nt < 8; nt++) {
                int c = bN + wn*64 + nt*8 + t*2;
                Cw[(size_t)r * (GN/2)       + (c >> 1)] = pk2(acc[mt][nt][0], acc[mt][nt][1]);
                Cw[(size_t)(r + 8) * (GN/2) + (c >> 1)] = pk2(acc[mt][nt][2], acc[mt][nt][3]);
            }
        }
    } else {
        float* C = (float*)Cv;
        #pragma unroll
        for (int mt = 0; mt < 4; mt++) {
            int r = bM + wm*64 + mt*16 + g;
            #pragma unroll
            for (int nt = 0; nt < 8; nt++) {
                int c = bN + wn*64 + nt*8 + t*2;
                *(float2*)&C[(size_t)r * GN + c]       = make_float2(acc[mt][nt][0], acc[mt][nt][1]);
                *(float2*)&C[(size_t)(r + 8) * GN + c] = make_float2(acc[mt][nt][2], acc[mt][nt][3]);
            }
        }
    }
}

// ------------------------------------------------------------------
// RoPE in place on half data
// ------------------------------------------------------------------
__global__ void rope_h(__half* __restrict__ P,
                       const float* __restrict__ cosT,
                       const float* __restrict__ sinT)
{
    int idx = blockIdx.x * blockDim.x + threadIdx.x;
    int hd  = idx & 63;
    int h   = (idx >> 6) & (Hh - 1);
    int row = idx >> 10;
    int s   = row & (Ss - 1);
    size_t base = (size_t)row * Dd + h * HDd;
    float q1 = __half2float(P[base + hd]);
    float q2 = __half2float(P[base + hd + 64]);
    float c1 = cosT[s*HDd + hd],      s1 = sinT[s*HDd + hd];
    float c2 = cosT[s*HDd + hd + 64], s2 = sinT[s*HDd + hd + 64];
    P[base + hd]      = __float2half_rn(q1 * c1 - q2 * s1);
    P[base + hd + 64] = __float2half_rn(q2 * c2 + q1 * s2);
}

// ------------------------------------------------------------------
// Flash attention, fp16. 64-query tiles, causal. 4 warps x 16 q rows.
// SMEM unit = half2 word. Row stride 68 words (64 data + 4 pad):
// fragment bank = 4g + t (distinct); ldmatrix rows 4*l groups (distinct).
// P never touches SMEM (C-frag -> A-frag register repack).
// ------------------------------------------------------------------
#define QT 64
#define ASTR 68
#define TW (QT*ASTR)            // 4352 words per tile buffer
#define ATTN_SMEM (5*TW*4)      // Q + 2K + 2V = 87040 B

__global__ __launch_bounds__(128) void attn_h()
{
    extern __shared__ uint32_t sw[];
    uint32_t* Qs = sw;              // [64][68]
    uint32_t* K0 = Qs + TW;
    uint32_t* K1 = K0 + TW;
    // V0 = K1+TW, V1 = V0+TW (byte addrs used below)

    const int tid  = threadIdx.x;
    const int lane = tid & 31, warp = tid >> 5;
    const int g = lane >> 2, t = lane & 3;
    const int qtile = blockIdx.x;
    const int bh = blockIdx.y;
    const int b  = bh >> 4, h = bh & 15;
    const int q0 = qtile * QT;

    const uint32_t sbase = smem_u32(sw);
    const uint32_t qa  = sbase;
    const uint32_t k0a = sbase + TW*4,   k1a = sbase + 2*TW*4;
    const uint32_t v0a = sbase + 3*TW*4, v1a = sbase + 4*TW*4;

    // fill mapping: chunk = 16B (8 halves); idx -> r = idx>>4, c = idx&15
    // dst word r*68 + c*4 -> conflict-free and fully coalesced.
    const size_t kvcol = (size_t)h * HDd;

    {   // prologue: Q tile + KV tile 0
        #pragma unroll
        for (int i = 0; i < 8; i++) {
            int idx = tid + i * 128;
            int r = idx >> 4, c = idx & 15;
            uint32_t dof = (uint32_t)(r*ASTR + c*4) * 4u;
            size_t gq = (size_t)(b*Ss + q0 + r) * Dd + kvcol + c*8;
            size_t gk = (size_t)(b*Ss + r) * Dd + kvcol + c*8;
            CP_ASYNC16(qa  + dof, g_Qh + gq);
            CP_ASYNC16(k0a + dof, g_Kh + gk);
            CP_ASYNC16(v0a + dof, g_Vh + gk);
        }
        CP_COMMIT();
    }

    float accO[16][4];
    #pragma unroll
    for (int nt = 0; nt < 16; nt++)
        #pragma unroll
        for (int e = 0; e < 4; e++) accO[nt][e] = 0.f;
    float m0 = -INFINITY, m1 = -INFINITY, l0 = 0.f, l1 = 0.f;

    const int row0 = q0 + warp*16 + g;
    const int row1 = row0 + 8;
    const int nj = qtile + 1;
    const int qr = warp*16 + g;
    const uint32_t vrow = (uint32_t)(lane & 15) * (ASTR*4);   // ldmatrix lane row offset

    for (int jt = 0; jt < nj; jt++) {
        CP_WAIT(0);
        __syncthreads();

        // prefetch next KV tile into the other buffer
        if (jt + 1 < nj) {
            const uint32_t ka = ((jt + 1) & 1) ? k1a : k0a;
            const uint32_t va = ((jt + 1) & 1) ? v1a : v0a;
            const int jrow = (jt + 1) * QT;
            #pragma unroll
            for (int i = 0; i < 8; i++) {
                int idx = tid + i * 128;
                int r = idx >> 4, c = idx & 15;
                uint32_t dof = (uint32_t)(r*ASTR + c*4) * 4u;
                size_t gk = (size_t)(b*Ss + jrow + r) * Dd + kvcol + c*8;
                CP_ASYNC16(ka + dof, g_Kh + gk);
                CP_ASYNC16(va + dof, g_Vh + gk);
            }
            CP_COMMIT();
        }

        const uint32_t* Ks = (jt & 1) ? K1 : K0;
        const uint32_t  va = (jt & 1) ? v1a : v0a;
        const int j = jt * QT;

        // ---- scores = Q K^T (warp: 16 x 64), 8 k16-chunks ----
        float sc[8][4];
        #pragma unroll
        for (int nt = 0; nt < 8; nt++)
            #pragma unroll
            for (int e = 0; e < 4; e++) sc[nt][e] = 0.f;

        #pragma unroll
        for (int ch = 0; ch < 8; ch++) {
            const int kk2 = ch * 8;
            uint32_t a[4];
            a[0] = Qs[qr*ASTR     + kk2 + t];
            a[1] = Qs[(qr+8)*ASTR + kk2 + t];
            a[2] = Qs[qr*ASTR     + kk2 + t + 4];
            a[3] = Qs[(qr+8)*ASTR + kk2 + t + 4];
            #pragma unroll
            for (int nt = 0; nt < 8; nt++) {
                int o = (nt*8 + g)*ASTR + kk2 + t;
                mma_f16(sc[nt], a, Ks[o], Ks[o + 4]);
            }
        }

        // ---- scale + causal mask (diagonal tile only) ----
        const bool diag = (jt == nj - 1);
        #pragma unroll
        for (int nt = 0; nt < 8; nt++) {
            int col = j + nt*8 + t*2;
            sc[nt][0] *= ATTN_SCALE; sc[nt][1] *= ATTN_SCALE;
            sc[nt][2] *= ATTN_SCALE; sc[nt][3] *= ATTN_SCALE;
            if (diag) {
                if (col     > row0) sc[nt][0] = -INFINITY;
                if (col + 1 > row0) sc[nt][1] = -INFINITY;
                if (col     > row1) sc[nt][2] = -INFINITY;
                if (col + 1 > row1) sc[nt][3] = -INFINITY;
            }
        }

        // ---- online softmax (P stays in registers as half2 packs) ----
        float rm0 = -INFINITY, rm1 = -INFINITY;
        #pragma unroll
        for (int nt = 0; nt < 8; nt++) {
            rm0 = fmaxf(rm0, fmaxf(sc[nt][0], sc[nt][1]));
            rm1 = fmaxf(rm1, fmaxf(sc[nt][2], sc[nt][3]));
        }
        rm0 = fmaxf(rm0, __shfl_xor_sync(0xffffffffu, rm0, 1));
        rm0 = fmaxf(rm0, __shfl_xor_sync(0xffffffffu, rm0, 2));
        rm1 = fmaxf(rm1, __shfl_xor_sync(0xffffffffu, rm1, 1));
        rm1 = fmaxf(rm1, __shfl_xor_sync(0xffffffffu, rm1, 2));

        float m0n = fmaxf(m0, rm0), m1n = fmaxf(m1, rm1);
        float al0 = __expf(m0 - m0n), al1 = __expf(m1 - m1n);
        float sum0 = 0.f, sum1 = 0.f;
        uint32_t ph[8][2];
        #pragma unroll
        for (int nt = 0; nt < 8; nt++) {
            float p0 = __expf(sc[nt][0] - m0n);
            float p1 = __expf(sc[nt][1] - m0n);
            float p2 = __expf(sc[nt][2] - m1n);
            float p3 = __expf(sc[nt][3] - m1n);
            sum0 += p0 + p1; sum1 += p2 + p3;
            ph[nt][0] = pk2(p0, p1);    // row g   (A-frag a0/a2 source)
            ph[nt][1] = pk2(p2, p3);    // row g+8 (A-frag a1/a3 source)
        }
        sum0 += __shfl_xor_sync(0xffffffffu, sum0, 1);
        sum0 += __shfl_xor_sync(0xffffffffu, sum0, 2);
        sum1 += __shfl_xor_sync(0xffffffffu, sum1, 1);
        sum1 += __shfl_xor_sync(0xffffffffu, sum1, 2);
        l0 = l0 * al0 + sum0;
        l1 = l1 * al1 + sum1;
        m0 = m0n; m1 = m1n;
        #pragma unroll
        for (int nt = 0; nt < 16; nt++) {
            accO[nt][0] *= al0; accO[nt][1] *= al0;
            accO[nt][2] *= al1; accO[nt][3] *= al1;
        }

        // ---- O += P V (warp: 16 x 128); V via ldmatrix.x2.trans ----
        #pragma unroll
        for (int kc = 0; kc < 4; kc++) {        // kv chunks of 16
            const int n0 = kc * 2;
            uint32_t a[4];
            a[0] = ph[n0][0];     a[1] = ph[n0][1];
            a[2] = ph[n0+1][0];   a[3] = ph[n0+1][1];
            const uint32_t vb = va + (uint32_t)(kc*16*ASTR)*4u + vrow;
            #pragma unroll
            for (int nt = 0; nt < 16; nt++) {
                uint32_t b0, b1;
                ldm_x2_t(b0, b1, vb + nt*16);
                mma_f16(accO[nt], a, b0, b1);
            }
        }
    }

    // ---- epilogue: normalize + pack to half ----
    float inv0 = 1.f / l0, inv1 = 1.f / l1;
    uint32_t* Aw = (uint32_t*)g_Ah;
    size_t ob0 = ((size_t)(b*Ss + q0 + warp*16 + g) * Dd + h * HDd) >> 1;
    size_t ob1 = ob0 + 4*Dd;   // +8 rows, in half2 words
    #pragma unroll
    for (int nt = 0; nt < 16; nt++) {
        int cw = nt*4 + t;
        Aw[ob0 + cw] = pk2(accO[nt][0] * inv0, accO[nt][1] * inv0);
        Aw[ob1 + cw] = pk2(accO[nt][2] * inv1, accO[nt][3] * inv1);
    }
}

// ============================================================
extern "C" void kernel_launch(void* const* d_in, const int* in_sizes, int n_in,
                              void* d_out, int out_size)
{
    (void)in_sizes; (void)n_in; (void)out_size;
    const float* x    = (const float*)d_in[0];
    // d_in[1] = mask (unused -- causal implemented directly)
    const float* cosT = (const float*)d_in[2];
    const float* sinT = (const float*)d_in[3];
    const float* Wq   = (const float*)d_in[4];
    const float* Wk   = (const float*)d_in[5];
    const float* Wv   = (const float*)d_in[6];
    const float* Wo   = (const float*)d_in[7];
    float* out = (float*)d_out;

    __half *xh, *wh, *qh, *kh, *vh, *ah;
    cudaGetSymbolAddress((void**)&xh, g_Xh);
    cudaGetSymbolAddress((void**)&wh, g_Wh);
    cudaGetSymbolAddress((void**)&qh, g_Qh);
    cudaGetSymbolAddress((void**)&kh, g_Kh);
    cudaGetSymbolAddress((void**)&vh, g_Vh);
    cudaGetSymbolAddress((void**)&ah, g_Ah);
    __half* wqh = wh;
    __half* wkh = wh + (size_t)Dd*Dd;
    __half* wvh = wh + 2*(size_t)Dd*Dd;
    __half* woh = wh + 3*(size_t)Dd*Dd;

    // pack inputs to fp16 (5 launches; also steers ncu -s 5 onto a GEMM)
    pack_half<<<(MROWS*Dd/4)/256, 256>>>((const float4*)x,  (uint32_t*)xh,  MROWS*Dd/4);
    pack_half<<<(Dd*Dd/4)/256, 256>>>((const float4*)Wq, (uint32_t*)wqh, Dd*Dd/4);
    pack_half<<<(Dd*Dd/4)/256, 256>>>((const float4*)Wk, (uint32_t*)wkh, Dd*Dd/4);
    pack_half<<<(Dd*Dd/4)/256, 256>>>((const float4*)Wv, (uint32_t*)wvh, Dd*Dd/4);
    pack_half<<<(Dd*Dd/4)/256, 256>>>((const float4*)Wo, (uint32_t*)woh, Dd*Dd/4);

    cudaFuncSetAttribute(gemm_h, cudaFuncAttributeMaxDynamicSharedMemorySize, G_SMEM);
    dim3 gg(GN / 256, GM / 128);   // (8, 32)
    gemm_h<<<gg, 256, G_SMEM>>>(xh, wqh, qh, 1);
    gemm_h<<<gg, 256, G_SMEM>>>(xh, wkh, kh, 1);
    gemm_h<<<gg, 256, G_SMEM>>>(xh, wvh, vh, 1);

    int nrope = MROWS * Hh * 64;
    rope_h<<<nrope / 256, 256>>>(qh, cosT, sinT);
    rope_h<<<nrope / 256, 256>>>(kh, cosT, sinT);

    cudaFuncSetAttribute(attn_h, cudaFuncAttributeMaxDynamicSharedMemorySize, ATTN_SMEM);
    attn_h<<<dim3(Ss / QT, Bb * Hh), 128, ATTN_SMEM>>>();

    gemm_h<<<gg, 256, G_SMEM>>>(ah, woh, out, 0);
}

// round 12
// speedup vs baseline: 3.5129x; 1.2090x over previous
#include <cuda_runtime.h>
#include <cuda_fp16.h>
#include <cstdint>

// Problem constants
#define Bb 2
#define Ss 2048
#define Dd 2048
#define Hh 16
#define HDd 128
#define MROWS (Bb*Ss)              // 4096
#define ATTN_SCALE 0.08838834764831845f  // 1/sqrt(128)

// Scratch (static device globals: allocation-free rule)
__device__ __half g_Xh[(size_t)MROWS*Dd];
__device__ __half g_Wh[4][(size_t)Dd*Dd];
__device__ __half g_Qh[(size_t)MROWS*Dd];
__device__ __half g_Kh[(size_t)MROWS*Dd];
__device__ __half g_Vh[(size_t)MROWS*Dd];
__device__ __half g_Ah[(size_t)MROWS*Dd];

// ------------------------------------------------------------------
// helpers
// ------------------------------------------------------------------
__device__ __forceinline__ uint32_t pk2(float a, float b){
    __half2 h = __floats2half2_rn(a, b);
    return *reinterpret_cast<uint32_t*>(&h);
}
__device__ __forceinline__ uint32_t smem_u32(const void* p){
    uint32_t a;
    asm("{ .reg .u64 t; cvta.to.shared.u64 t, %1; cvt.u32.u64 %0, t; }"
        : "=r"(a) : "l"(p));
    return a;
}
__device__ __forceinline__ void mma_f16(float c[4], const uint32_t a[4],
                                        uint32_t b0, uint32_t b1){
    asm volatile("mma.sync.aligned.m16n8k16.row.col.f32.f16.f16.f32 "
        "{%0,%1,%2,%3}, {%4,%5,%6,%7}, {%8,%9}, {%0,%1,%2,%3};\n"
        : "+f"(c[0]), "+f"(c[1]), "+f"(c[2]), "+f"(c[3])
        : "r"(a[0]), "r"(a[1]), "r"(a[2]), "r"(a[3]), "r"(b0), "r"(b1));
}
__device__ __forceinline__ void ldm_x4(uint32_t &r0, uint32_t &r1,
                                       uint32_t &r2, uint32_t &r3, uint32_t addr){
    asm volatile("ldmatrix.sync.aligned.m8n8.x4.shared.b16 {%0,%1,%2,%3}, [%4];"
        : "=r"(r0), "=r"(r1), "=r"(r2), "=r"(r3) : "r"(addr));
}
__device__ __forceinline__ void ldm_x4_t(uint32_t &r0, uint32_t &r1,
                                         uint32_t &r2, uint32_t &r3, uint32_t addr){
    asm volatile("ldmatrix.sync.aligned.m8n8.x4.trans.shared.b16 {%0,%1,%2,%3}, [%4];"
        : "=r"(r0), "=r"(r1), "=r"(r2), "=r"(r3) : "r"(addr));
}

#define CP_ASYNC16(sa, ga) \
    asm volatile("cp.async.cg.shared.global [%0], [%1], 16;" :: "r"(sa), "l"(ga))
#define CP_COMMIT() asm volatile("cp.async.commit_group;" ::: "memory")
#define CP_WAIT(n)  asm volatile("cp.async.wait_group %0;" :: "n"(n) : "memory")

// ------------------------------------------------------------------
// pack fp32 -> fp16
// ------------------------------------------------------------------
__global__ void pack_half(const float4* __restrict__ in, uint32_t* __restrict__ out,
                          int n4){
    int i = blockIdx.x * blockDim.x + threadIdx.x;
    if (i < n4) {
        float4 v = in[i];
        out[2*i]   = pk2(v.x, v.y);
        out[2*i+1] = pk2(v.z, v.w);
    }
}

// ------------------------------------------------------------------
// GEMM: C[M,N] = A[M,K] * W[N,K]^T   (fp16 m16n8k16, fp32 accum)
// 128x128 block, 8 warps (4x2) of 32x64, BK=32 halves, 4-stage cp.async,
// 2 CTAs/SM (80KB smem, <=128 regs). Fragments via ldmatrix.x4.
// SMEM row = 16 half2 words + 4 pad (SSTR=20): ldmatrix phases conflict-free.
// ------------------------------------------------------------------
#define GM 4096
#define GN 2048
#define GK 2048
#define BKH 32                          // halves per k-tile
#define SSTR 20                         // words per smem row
#define A_WORDS (128*SSTR)              // 2560
#define B_WORDS (128*SSTR)              // 2560
#define STG_WORDS (A_WORDS + B_WORDS)   // 5120 words = 20480 B
#define G_STAGES 4
#define G_SMEM (G_STAGES*STG_WORDS*4)   // 81920 B
#define G_NK (GK/BKH)                   // 64

__global__ __launch_bounds__(256, 2) void gemm_h(const __half* __restrict__ A,
                                                 const __half* __restrict__ W,
                                                 void* __restrict__ Cv,
                                                 int outh)
{
    extern __shared__ uint32_t smw[];
    const int tid  = threadIdx.x;
    const int lane = tid & 31, warp = tid >> 5;
    const int wm = warp >> 1, wn = warp & 1;      // 4 x 2 warp grid (32x64 tiles)
    const int g = lane >> 2, t = lane & 3;
    const int bM = blockIdx.y * 128, bN = blockIdx.x * 128;

    // fill: chunk = 16B (8 halves); A 512 chunks, B 512 chunks, 2+2 per thread
    const int frow = tid >> 2, fc = tid & 3;
    const __half* Ag = A + (size_t)(bM + frow) * GK + fc * 8;
    const __half* Wg = W + (size_t)(bN + frow) * GK + fc * 8;
    const uint32_t smem_base = smem_u32(smw);
    const uint32_t fillA = smem_base + (uint32_t)(frow * SSTR + fc * 4) * 4u;
    const uint32_t fillB = smem_base + (uint32_t)(A_WORDS + frow * SSTR + fc * 4) * 4u;

    // ldmatrix lane address components
    const int a_row = wm*32 + (lane & 15);                 // + mt*16
    const int a_col = (lane >> 4) << 2;                    // + ks*8
    const int b_row = wn*64 + (lane & 7) + ((lane >> 4) << 3);   // + p*16
    const int b_col = ((lane >> 3) & 1) << 2;              // + ks*8
    const uint32_t aoff = (uint32_t)(a_row * SSTR + a_col) * 4u;
    const uint32_t boff = (uint32_t)(A_WORDS + b_row * SSTR + b_col) * 4u;

    float acc[2][8][4];
    #pragma unroll
    for (int mt = 0; mt < 2; mt++)
        #pragma unroll
        for (int nt = 0; nt < 8; nt++)
            #pragma unroll
            for (int e = 0; e < 4; e++) acc[mt][nt][e] = 0.f;

    // prologue: fill stages 0..2
    #pragma unroll
    for (int s = 0; s < G_STAGES - 1; s++) {
        uint32_t sa = fillA + s * (STG_WORDS * 4);
        uint32_t sw = fillB + s * (STG_WORDS * 4);
        const __half* ap = Ag + s * BKH;
        const __half* wp = Wg + s * BKH;
        CP_ASYNC16(sa, ap);
        CP_ASYNC16(sa + 64*SSTR*4, ap + (size_t)64 * GK);
        CP_ASYNC16(sw, wp);
        CP_ASYNC16(sw + 64*SSTR*4, wp + (size_t)64 * GK);
        CP_COMMIT();
    }

    for (int kt = 0; kt < G_NK; kt++) {
        CP_WAIT(2);
        __syncthreads();

        {   // prefetch tile kt+3 into slot (kt+3)%4
            const int pf = kt + G_STAGES - 1;
            if (pf < G_NK) {
                const int sp = pf & (G_STAGES - 1);
                uint32_t sa = fillA + sp * (STG_WORDS * 4);
                uint32_t sw = fillB + sp * (STG_WORDS * 4);
                const __half* ap = Ag + pf * BKH;
                const __half* wp = Wg + pf * BKH;
                CP_ASYNC16(sa, ap);
                CP_ASYNC16(sa + 64*SSTR*4, ap + (size_t)64 * GK);
                CP_ASYNC16(sw, wp);
                CP_ASYNC16(sw + 64*SSTR*4, wp + (size_t)64 * GK);
            }
            CP_COMMIT();
        }

        const uint32_t sbase = smem_base + (kt & (G_STAGES - 1)) * (STG_WORDS * 4);
        #pragma unroll
        for (int ks = 0; ks < 2; ks++) {        // k halves 0-15, 16-31
            const uint32_t kso = (uint32_t)(ks * 8) * 4u;
            uint32_t af[2][4], bf[8][2];
            #pragma unroll
            for (int mt = 0; mt < 2; mt++)
                ldm_x4(af[mt][0], af[mt][1], af[mt][2], af[mt][3],
                       sbase + aoff + kso + (uint32_t)(mt*16*SSTR)*4u);
            #pragma unroll
            for (int p = 0; p < 4; p++)
                ldm_x4(bf[2*p][0], bf[2*p][1], bf[2*p+1][0], bf[2*p+1][1],
                       sbase + boff + kso + (uint32_t)(p*16*SSTR)*4u);
            #pragma unroll
            for (int mt = 0; mt < 2; mt++)
                #pragma unroll
                for (int nt = 0; nt < 8; nt++)
                    mma_f16(acc[mt][nt], af[mt], bf[nt][0], bf[nt][1]);
        }
        __syncthreads();
    }

    // epilogue
    if (outh) {
        uint32_t* Cw = (uint32_t*)Cv;   // half2 words
        #pragma unroll
        for (int mt = 0; mt < 2; mt++) {
            int r = bM + wm*32 + mt*16 + g;
            #pragma unroll
            for (int nt = 0; nt < 8; nt++) {
                int c = bN + wn*64 + nt*8 + t*2;
                Cw[(size_t)r * (GN/2)       + (c >> 1)] = pk2(acc[mt][nt][0], acc[mt][nt][1]);
                Cw[(size_t)(r + 8) * (GN/2) + (c >> 1)] = pk2(acc[mt][nt][2], acc[mt][nt][3]);
            }
        }
    } else {
        float* C = (float*)Cv;
        #pragma unroll
        for (int mt = 0; mt < 2; mt++) {
            int r = bM + wm*32 + mt*16 + g;
            #pragma unroll
            for (int nt = 0; nt < 8; nt++) {
                int c = bN + wn*64 + nt*8 + t*2;
                *(float2*)&C[(size_t)r * GN + c]       = make_float2(acc[mt][nt][0], acc[mt][nt][1]);
                *(float2*)&C[(size_t)(r + 8) * GN + c] = make_float2(acc[mt][nt][2], acc[mt][nt][3]);
            }
        }
    }
}

// ------------------------------------------------------------------
// RoPE in place on half data
// ------------------------------------------------------------------
__global__ void rope_h(__half* __restrict__ P,
                       const float* __restrict__ cosT,
                       const float* __restrict__ sinT)
{
    int idx = blockIdx.x * blockDim.x + threadIdx.x;
    int hd  = idx & 63;
    int h   = (idx >> 6) & (Hh - 1);
    int row = idx >> 10;
    int s   = row & (Ss - 1);
    size_t base = (size_t)row * Dd + h * HDd;
    float q1 = __half2float(P[base + hd]);
    float q2 = __half2float(P[base + hd + 64]);
    float c1 = cosT[s*HDd + hd],      s1 = sinT[s*HDd + hd];
    float c2 = cosT[s*HDd + hd + 64], s2 = sinT[s*HDd + hd + 64];
    P[base + hd]      = __float2half_rn(q1 * c1 - q2 * s1);
    P[base + hd + 64] = __float2half_rn(q2 * c2 + q1 * s2);
}

// ------------------------------------------------------------------
// Flash attention, fp16, ldmatrix everywhere. 64-query tiles, causal.
// 4 warps x 16 q rows; heavy tiles launched first (reversed blockIdx.x).
// SMEM stride 68 words: all ldmatrix phases conflict-free.
// ------------------------------------------------------------------
#define QT 64
#define ASTR 68
#define TW (QT*ASTR)            // 4352 words per tile buffer
#define ATTN_SMEM (5*TW*4)      // Q + 2K + 2V = 87040 B

__global__ __launch_bounds__(128) void attn_h()
{
    extern __shared__ uint32_t sw[];
    const int tid  = threadIdx.x;
    const int lane = tid & 31, warp = tid >> 5;
    const int t = lane & 3;
    const int qtile = (gridDim.x - 1) - blockIdx.x;   // heavy tiles first
    const int bh = blockIdx.y;
    const int b  = bh >> 4, h = bh & 15;
    const int q0 = qtile * QT;

    const uint32_t sbase = smem_u32(sw);
    const uint32_t qa  = sbase;
    const uint32_t k0a = sbase + TW*4,   k1a = sbase + 2*TW*4;
    const uint32_t v0a = sbase + 3*TW*4, v1a = sbase + 4*TW*4;

    const size_t kvcol = (size_t)h * HDd;

    {   // prologue: Q tile + KV tile 0
        #pragma unroll
        for (int i = 0; i < 8; i++) {
            int idx = tid + i * 128;
            int r = idx >> 4, c = idx & 15;
            uint32_t dof = (uint32_t)(r*ASTR + c*4) * 4u;
            size_t gq = (size_t)(b*Ss + q0 + r) * Dd + kvcol + c*8;
            size_t gk = (size_t)(b*Ss + r) * Dd + kvcol + c*8;
            CP_ASYNC16(qa  + dof, g_Qh + gq);
            CP_ASYNC16(k0a + dof, g_Kh + gk);
            CP_ASYNC16(v0a + dof, g_Vh + gk);
        }
        CP_COMMIT();
    }

    // ldmatrix lane address components (stride ASTR)
    const uint32_t q_off = (uint32_t)((warp*16 + (lane & 15)) * ASTR
                                      + ((lane >> 4) << 2)) * 4u;            // + ch*8 words
    const uint32_t k_off = (uint32_t)(((lane & 7) + ((lane >> 4) << 3)) * ASTR
                                      + (((lane >> 3) & 1) << 2)) * 4u;      // + ntp*16 rows + ch*8
    const uint32_t v_off = (uint32_t)((lane & 15) * ASTR) * 4u
                         + ((uint32_t)(lane >> 4) << 4);                     // + kc*16 rows + nt pair*32B

    float accO[16][4];
    #pragma unroll
    for (int nt = 0; nt < 16; nt++)
        #pragma unroll
        for (int e = 0; e < 4; e++) accO[nt][e] = 0.f;
    float m0 = -INFINITY, m1 = -INFINITY, l0 = 0.f, l1 = 0.f;

    const int g = lane >> 2;
    const int row0 = q0 + warp*16 + g;
    const int row1 = row0 + 8;
    const int nj = qtile + 1;

    for (int jt = 0; jt < nj; jt++) {
        CP_WAIT(0);
        __syncthreads();

        // prefetch next KV tile into the other buffer
        if (jt + 1 < nj) {
            const uint32_t ka = ((jt + 1) & 1) ? k1a : k0a;
            const uint32_t va = ((jt + 1) & 1) ? v1a : v0a;
            const int jrow = (jt + 1) * QT;
            #pragma unroll
            for (int i = 0; i < 8; i++) {
                int idx = tid + i * 128;
                int r = idx >> 4, c = idx & 15;
                uint32_t dof = (uint32_t)(r*ASTR + c*4) * 4u;
                size_t gk = (size_t)(b*Ss + jrow + r) * Dd + kvcol + c*8;
                CP_ASYNC16(ka + dof, g_Kh + gk);
                CP_ASYNC16(va + dof, g_Vh + gk);
            }
            CP_COMMIT();
        }

        const uint32_t ka = (jt & 1) ? k1a : k0a;
        const uint32_t va = (jt & 1) ? v1a : v0a;
        const int j = jt * QT;

        // ---- scores = Q K^T (warp: 16 x 64), 8 k16-chunks ----
        float sc[8][4];
        #pragma unroll
        for (int nt = 0; nt < 8; nt++)
            #pragma unroll
            for (int e = 0; e < 4; e++) sc[nt][e] = 0.f;

        #pragma unroll
        for (int ch = 0; ch < 8; ch++) {
            const uint32_t kso = (uint32_t)(ch * 8) * 4u;
            uint32_t a[4], bf[8][2];
            ldm_x4(a[0], a[1], a[2], a[3], qa + q_off + kso);
            #pragma unroll
            for (int p = 0; p < 4; p++)
                ldm_x4(bf[2*p][0], bf[2*p][1], bf[2*p+1][0], bf[2*p+1][1],
                       ka + k_off + kso + (uint32_t)(p*16*ASTR)*4u);
            #pragma unroll
            for (int nt = 0; nt < 8; nt++)
                mma_f16(sc[nt], a, bf[nt][0], bf[nt][1]);
        }

        // ---- scale + causal mask (diagonal tile only) ----
        const bool diag = (jt == nj - 1);
        #pragma unroll
        for (int nt = 0; nt < 8; nt++) {
            int col = j + nt*8 + t*2;
            sc[nt][0] *= ATTN_SCALE; sc[nt][1] *= ATTN_SCALE;
            sc[nt][2] *= ATTN_SCALE; sc[nt][3] *= ATTN_SCALE;
            if (diag) {
                if (col     > row0) sc[nt][0] = -INFINITY;
                if (col + 1 > row0) sc[nt][1] = -INFINITY;
                if (col     > row1) sc[nt][2] = -INFINITY;
                if (col + 1 > row1) sc[nt][3] = -INFINITY;
            }
        }

        // ---- online softmax (P stays in registers) ----
        float rm0 = -INFINITY, rm1 = -INFINITY;
        #pragma unroll
        for (int nt = 0; nt < 8; nt++) {
            rm0 = fmaxf(rm0, fmaxf(sc[nt][0], sc[nt][1]));
            rm1 = fmaxf(rm1, fmaxf(sc[nt][2], sc[nt][3]));
        }
        rm0 = fmaxf(rm0, __shfl_xor_sync(0xffffffffu, rm0, 1));
        rm0 = fmaxf(rm0, __shfl_xor_sync(0xffffffffu, rm0, 2));
        rm1 = fmaxf(rm1, __shfl_xor_sync(0xffffffffu, rm1, 1));
        rm1 = fmaxf(rm1, __shfl_xor_sync(0xffffffffu, rm1, 2));

        float m0n = fmaxf(m0, rm0), m1n = fmaxf(m1, rm1);
        float al0 = __expf(m0 - m0n), al1 = __expf(m1 - m1n);
        float sum0 = 0.f, sum1 = 0.f;
        uint32_t ph[8][2];
        #pragma unroll
        for (int nt = 0; nt < 8; nt++) {
            float p0 = __expf(sc[nt][0] - m0n);
            float p1 = __expf(sc[nt][1] - m0n);
            float p2 = __expf(sc[nt][2] - m1n);
            float p3 = __expf(sc[nt][3] - m1n);
            sum0 += p0 + p1; sum1 += p2 + p3;
            ph[nt][0] = pk2(p0, p1);
            ph[nt][1] = pk2(p2, p3);
        }
        sum0 += __shfl_xor_sync(0xffffffffu, sum0, 1);
        sum0 += __shfl_xor_sync(0xffffffffu, sum0, 2);
        sum1 += __shfl_xor_sync(0xffffffffu, sum1, 1);
        sum1 += __shfl_xor_sync(0xffffffffu, sum1, 2);
        l0 = l0 * al0 + sum0;
        l1 = l1 * al1 + sum1;
        m0 = m0n; m1 = m1n;
        #pragma unroll
        for (int nt = 0; nt < 16; nt++) {
            accO[nt][0] *= al0; accO[nt][1] *= al0;
            accO[nt][2] *= al1; accO[nt][3] *= al1;
        }

        // ---- O += P V (warp: 16 x 128); V via ldmatrix.x4.trans ----
        #pragma unroll
        for (int kc = 0; kc < 4; kc++) {        // kv chunks of 16
            const int n0 = kc * 2;
            uint32_t a[4];
            a[0] = ph[n0][0];     a[1] = ph[n0][1];
            a[2] = ph[n0+1][0];   a[3] = ph[n0+1][1];
            const uint32_t vb = va + (uint32_t)(kc*16*ASTR)*4u + v_off;
            #pragma unroll
            for (int np = 0; np < 8; np++) {    // nt pairs
                uint32_t b0, b1, b2, b3;
                ldm_x4_t(b0, b1, b2, b3, vb + np*32);
                mma_f16(accO[2*np],   a, b0, b1);
                mma_f16(accO[2*np+1], a, b2, b3);
            }
        }
    }

    // ---- epilogue: normalize + pack to half ----
    float inv0 = 1.f / l0, inv1 = 1.f / l1;
    uint32_t* Aw = (uint32_t*)g_Ah;
    size_t ob0 = ((size_t)(b*Ss + q0 + warp*16 + g) * Dd + h * HDd) >> 1;
    size_t ob1 = ob0 + 4*Dd;   // +8 rows, in half2 words
    #pragma unroll
    for (int nt = 0; nt < 16; nt++) {
        int cw = nt*4 + t;
        Aw[ob0 + cw] = pk2(accO[nt][0] * inv0, accO[nt][1] * inv0);
        Aw[ob1 + cw] = pk2(accO[nt][2] * inv1, accO[nt][3] * inv1);
    }
}

// ============================================================
extern "C" void kernel_launch(void* const* d_in, const int* in_sizes, int n_in,
                              void* d_out, int out_size)
{
    (void)in_sizes; (void)n_in; (void)out_size;
    const float* x    = (const float*)d_in[0];
    // d_in[1] = mask (unused -- causal implemented directly)
    const float* cosT = (const float*)d_in[2];
    const float* sinT = (const float*)d_in[3];
    const float* Wq   = (const float*)d_in[4];
    const float* Wk   = (const float*)d_in[5];
    const float* Wv   = (const float*)d_in[6];
    const float* Wo   = (const float*)d_in[7];
    float* out = (float*)d_out;

    __half *xh, *wh, *qh, *kh, *vh, *ah;
    cudaGetSymbolAddress((void**)&xh, g_Xh);
    cudaGetSymbolAddress((void**)&wh, g_Wh);
    cudaGetSymbolAddress((void**)&qh, g_Qh);
    cudaGetSymbolAddress((void**)&kh, g_Kh);
    cudaGetSymbolAddress((void**)&vh, g_Vh);
    cudaGetSymbolAddress((void**)&ah, g_Ah);
    __half* wqh = wh;
    __half* wkh = wh + (size_t)Dd*Dd;
    __half* wvh = wh + 2*(size_t)Dd*Dd;
    __half* woh = wh + 3*(size_t)Dd*Dd;

    pack_half<<<(MROWS*Dd/4)/256, 256>>>((const float4*)x,  (uint32_t*)xh,  MROWS*Dd/4);
    pack_half<<<(Dd*Dd/4)/256, 256>>>((const float4*)Wq, (uint32_t*)wqh, Dd*Dd/4);
    pack_half<<<(Dd*Dd/4)/256, 256>>>((const float4*)Wk, (uint32_t*)wkh, Dd*Dd/4);
    pack_half<<<(Dd*Dd/4)/256, 256>>>((const float4*)Wv, (uint32_t*)wvh, Dd*Dd/4);
    pack_half<<<(Dd*Dd/4)/256, 256>>>((const float4*)Wo, (uint32_t*)woh, Dd*Dd/4);

    cudaFuncSetAttribute(gemm_h, cudaFuncAttributeMaxDynamicSharedMemorySize, G_SMEM);
    dim3 gg(GN / 128, GM / 128);   // (16, 32)
    gemm_h<<<gg, 256, G_SMEM>>>(xh, wqh, qh, 1);
    gemm_h<<<gg, 256, G_SMEM>>>(xh, wkh, kh, 1);
    gemm_h<<<gg, 256, G_SMEM>>>(xh, wvh, vh, 1);

    int nrope = MROWS * Hh * 64;
    rope_h<<<nrope / 256, 256>>>(qh, cosT, sinT);
    rope_h<<<nrope / 256, 256>>>(kh, cosT, sinT);

    cudaFuncSetAttribute(attn_h, cudaFuncAttributeMaxDynamicSharedMemorySize, ATTN_SMEM);
    attn_h<<<dim3(Ss / QT, Bb * Hh), 128, ATTN_SMEM>>>();

    gemm_h<<<gg, 256, G_SMEM>>>(ah, woh, out, 0);
}

// round 13
// speedup vs baseline: 3.6770x; 1.0467x over previous
#include <cuda_runtime.h>
#include <cuda_fp16.h>
#include <cstdint>

// Problem constants
#define Bb 2
#define Ss 2048
#define Dd 2048
#define Hh 16
#define HDd 128
#define MROWS (Bb*Ss)              // 4096
#define ATTN_SCALE 0.08838834764831845f  // 1/sqrt(128)

// Scratch (static device globals: allocation-free rule)
__device__ __half g_Xh[(size_t)MROWS*Dd];
__device__ __half g_Wh[4][(size_t)Dd*Dd];
__device__ __half g_Qh[(size_t)MROWS*Dd];
__device__ __half g_Kh[(size_t)MROWS*Dd];
__device__ __half g_Vh[(size_t)MROWS*Dd];
__device__ __half g_Ah[(size_t)MROWS*Dd];

// ------------------------------------------------------------------
// helpers
// ------------------------------------------------------------------
__device__ __forceinline__ uint32_t pk2(float a, float b){
    __half2 h = __floats2half2_rn(a, b);
    return *reinterpret_cast<uint32_t*>(&h);
}
__device__ __forceinline__ uint32_t smem_u32(const void* p){
    uint32_t a;
    asm("{ .reg .u64 t; cvta.to.shared.u64 t, %1; cvt.u32.u64 %0, t; }"
        : "=r"(a) : "l"(p));
    return a;
}
__device__ __forceinline__ void mma_f16(float c[4], const uint32_t a[4],
                                        uint32_t b0, uint32_t b1){
    asm volatile("mma.sync.aligned.m16n8k16.row.col.f32.f16.f16.f32 "
        "{%0,%1,%2,%3}, {%4,%5,%6,%7}, {%8,%9}, {%0,%1,%2,%3};\n"
        : "+f"(c[0]), "+f"(c[1]), "+f"(c[2]), "+f"(c[3])
        : "r"(a[0]), "r"(a[1]), "r"(a[2]), "r"(a[3]), "r"(b0), "r"(b1));
}
__device__ __forceinline__ void ldm_x4(uint32_t &r0, uint32_t &r1,
                                       uint32_t &r2, uint32_t &r3, uint32_t addr){
    asm volatile("ldmatrix.sync.aligned.m8n8.x4.shared.b16 {%0,%1,%2,%3}, [%4];"
        : "=r"(r0), "=r"(r1), "=r"(r2), "=r"(r3) : "r"(addr));
}
__device__ __forceinline__ void ldm_x4_t(uint32_t &r0, uint32_t &r1,
                                         uint32_t &r2, uint32_t &r3, uint32_t addr){
    asm volatile("ldmatrix.sync.aligned.m8n8.x4.trans.shared.b16 {%0,%1,%2,%3}, [%4];"
        : "=r"(r0), "=r"(r1), "=r"(r2), "=r"(r3) : "r"(addr));
}

#define CP_ASYNC16(sa, ga) \
    asm volatile("cp.async.cg.shared.global [%0], [%1], 16;" :: "r"(sa), "l"(ga))
#define CP_COMMIT() asm volatile("cp.async.commit_group;" ::: "memory")
#define CP_WAIT(n)  asm volatile("cp.async.wait_group %0;" :: "n"(n) : "memory")

// ------------------------------------------------------------------
// pack fp32 -> fp16
// ------------------------------------------------------------------
__global__ void pack_half(const float4* __restrict__ in, uint32_t* __restrict__ out,
                          int n4){
    int i = blockIdx.x * blockDim.x + threadIdx.x;
    if (i < n4) {
        float4 v = in[i];
        out[2*i]   = pk2(v.x, v.y);
        out[2*i+1] = pk2(v.z, v.w);
    }
}
// dual-weight pack (blockIdx.y selects source)
__global__ void pack_half2(const float4* __restrict__ in0, uint32_t* __restrict__ out0,
                           const float4* __restrict__ in1, uint32_t* __restrict__ out1,
                           int n4){
    int i = blockIdx.x * blockDim.x + threadIdx.x;
    if (i >= n4) return;
    const float4* in = blockIdx.y ? in1 : in0;
    uint32_t* out = blockIdx.y ? out1 : out0;
    float4 v = in[i];
    out[2*i]   = pk2(v.x, v.y);
    out[2*i+1] = pk2(v.z, v.w);
}

// ------------------------------------------------------------------
// GEMM: C[M,N] = A[M,K] * W[N,K]^T   (fp16 m16n8k16, fp32 accum)
// 128x128 block, 8 warps (4x2) of 32x64, BK=32 halves, 4-stage cp.async,
// 2 CTAs/SM. Fragments via ldmatrix.x4. (unchanged from R12)
// ------------------------------------------------------------------
#define GM 4096
#define GN 2048
#define GK 2048
#define BKH 32
#define SSTR 20
#define A_WORDS (128*SSTR)
#define B_WORDS (128*SSTR)
#define STG_WORDS (A_WORDS + B_WORDS)
#define G_STAGES 4
#define G_SMEM (G_STAGES*STG_WORDS*4)   // 81920 B
#define G_NK (GK/BKH)

__global__ __launch_bounds__(256, 2) void gemm_h(const __half* __restrict__ A,
                                                 const __half* __restrict__ W,
                                                 void* __restrict__ Cv,
                                                 int outh)
{
    extern __shared__ uint32_t smw[];
    const int tid  = threadIdx.x;
    const int lane = tid & 31, warp = tid >> 5;
    const int wm = warp >> 1, wn = warp & 1;
    const int g = lane >> 2, t = lane & 3;
    const int bM = blockIdx.y * 128, bN = blockIdx.x * 128;

    const int frow = tid >> 2, fc = tid & 3;
    const __half* Ag = A + (size_t)(bM + frow) * GK + fc * 8;
    const __half* Wg = W + (size_t)(bN + frow) * GK + fc * 8;
    const uint32_t smem_base = smem_u32(smw);
    const uint32_t fillA = smem_base + (uint32_t)(frow * SSTR + fc * 4) * 4u;
    const uint32_t fillB = smem_base + (uint32_t)(A_WORDS + frow * SSTR + fc * 4) * 4u;

    const int a_row = wm*32 + (lane & 15);
    const int a_col = (lane >> 4) << 2;
    const int b_row = wn*64 + (lane & 7) + ((lane >> 4) << 3);
    const int b_col = ((lane >> 3) & 1) << 2;
    const uint32_t aoff = (uint32_t)(a_row * SSTR + a_col) * 4u;
    const uint32_t boff = (uint32_t)(A_WORDS + b_row * SSTR + b_col) * 4u;

    float acc[2][8][4];
    #pragma unroll
    for (int mt = 0; mt < 2; mt++)
        #pragma unroll
        for (int nt = 0; nt < 8; nt++)
            #pragma unroll
            for (int e = 0; e < 4; e++) acc[mt][nt][e] = 0.f;

    #pragma unroll
    for (int s = 0; s < G_STAGES - 1; s++) {
        uint32_t sa = fillA + s * (STG_WORDS * 4);
        uint32_t sw = fillB + s * (STG_WORDS * 4);
        const __half* ap = Ag + s * BKH;
        const __half* wp = Wg + s * BKH;
        CP_ASYNC16(sa, ap);
        CP_ASYNC16(sa + 64*SSTR*4, ap + (size_t)64 * GK);
        CP_ASYNC16(sw, wp);
        CP_ASYNC16(sw + 64*SSTR*4, wp + (size_t)64 * GK);
        CP_COMMIT();
    }

    for (int kt = 0; kt < G_NK; kt++) {
        CP_WAIT(2);
        __syncthreads();

        {
            const int pf = kt + G_STAGES - 1;
            if (pf < G_NK) {
                const int sp = pf & (G_STAGES - 1);
                uint32_t sa = fillA + sp * (STG_WORDS * 4);
                uint32_t sw = fillB + sp * (STG_WORDS * 4);
                const __half* ap = Ag + pf * BKH;
                const __half* wp = Wg + pf * BKH;
                CP_ASYNC16(sa, ap);
                CP_ASYNC16(sa + 64*SSTR*4, ap + (size_t)64 * GK);
                CP_ASYNC16(sw, wp);
                CP_ASYNC16(sw + 64*SSTR*4, wp + (size_t)64 * GK);
            }
            CP_COMMIT();
        }

        const uint32_t sbase = smem_base + (kt & (G_STAGES - 1)) * (STG_WORDS * 4);
        #pragma unroll
        for (int ks = 0; ks < 2; ks++) {
            const uint32_t kso = (uint32_t)(ks * 8) * 4u;
            uint32_t af[2][4], bf[8][2];
            #pragma unroll
            for (int mt = 0; mt < 2; mt++)
                ldm_x4(af[mt][0], af[mt][1], af[mt][2], af[mt][3],
                       sbase + aoff + kso + (uint32_t)(mt*16*SSTR)*4u);
            #pragma unroll
            for (int p = 0; p < 4; p++)
                ldm_x4(bf[2*p][0], bf[2*p][1], bf[2*p+1][0], bf[2*p+1][1],
                       sbase + boff + kso + (uint32_t)(p*16*SSTR)*4u);
            #pragma unroll
            for (int mt = 0; mt < 2; mt++)
                #pragma unroll
                for (int nt = 0; nt < 8; nt++)
                    mma_f16(acc[mt][nt], af[mt], bf[nt][0], bf[nt][1]);
        }
        __syncthreads();
    }

    if (outh) {
        uint32_t* Cw = (uint32_t*)Cv;
        #pragma unroll
        for (int mt = 0; mt < 2; mt++) {
            int r = bM + wm*32 + mt*16 + g;
            #pragma unroll
            for (int nt = 0; nt < 8; nt++) {
                int c = bN + wn*64 + nt*8 + t*2;
                Cw[(size_t)r * (GN/2)       + (c >> 1)] = pk2(acc[mt][nt][0], acc[mt][nt][1]);
                Cw[(size_t)(r + 8) * (GN/2) + (c >> 1)] = pk2(acc[mt][nt][2], acc[mt][nt][3]);
            }
        }
    } else {
        float* C = (float*)Cv;
        #pragma unroll
        for (int mt = 0; mt < 2; mt++) {
            int r = bM + wm*32 + mt*16 + g;
            #pragma unroll
            for (int nt = 0; nt < 8; nt++) {
                int c = bN + wn*64 + nt*8 + t*2;
                *(float2*)&C[(size_t)r * GN + c]       = make_float2(acc[mt][nt][0], acc[mt][nt][1]);
                *(float2*)&C[(size_t)(r + 8) * GN + c] = make_float2(acc[mt][nt][2], acc[mt][nt][3]);
            }
        }
    }
}

// ------------------------------------------------------------------
// RoPE in place on half data (grid.y selects Q or K)
// ------------------------------------------------------------------
__global__ void rope_h2(__half* __restrict__ Pq, __half* __restrict__ Pk,
                        const float* __restrict__ cosT,
                        const float* __restrict__ sinT)
{
    __half* P = blockIdx.y ? Pk : Pq;
    int idx = blockIdx.x * blockDim.x + threadIdx.x;
    int hd  = idx & 63;
    int h   = (idx >> 6) & (Hh - 1);
    int row = idx >> 10;
    int s   = row & (Ss - 1);
    size_t base = (size_t)row * Dd + h * HDd;
    float q1 = __half2float(P[base + hd]);
    float q2 = __half2float(P[base + hd + 64]);
    float c1 = cosT[s*HDd + hd],      s1 = sinT[s*HDd + hd];
    float c2 = cosT[s*HDd + hd + 64], s2 = sinT[s*HDd + hd + 64];
    P[base + hd]      = __float2half_rn(q1 * c1 - q2 * s1);
    P[base + hd + 64] = __float2half_rn(q2 * c2 + q1 * s2);
}

// ------------------------------------------------------------------
// Flash attention, fp16, ldmatrix. 128-query tiles, 64-row KV tiles,
// causal. 8 warps x 16 q rows, 256 threads, 102KB smem -> 2 CTAs/SM
// = 16 warps/SM. Heavy tiles first.
// ------------------------------------------------------------------
#define QTA 128
#define KTA 64
#define ASTR 68
#define QWRD (QTA*ASTR)         // 8704 words
#define KWRD (KTA*ASTR)         // 4352 words per KV buffer
#define ATTN_SMEM ((QWRD + 4*KWRD)*4)   // 104448 B

__global__ __launch_bounds__(256, 2) void attn_h()
{
    extern __shared__ uint32_t sw[];
    const int tid  = threadIdx.x;
    const int lane = tid & 31, warp = tid >> 5;
    const int t = lane & 3;
    const int qtile = (gridDim.x - 1) - blockIdx.x;   // heavy tiles first
    const int bh = blockIdx.y;
    const int b  = bh >> 4, h = bh & 15;
    const int q0 = qtile * QTA;

    const uint32_t sbase = smem_u32(sw);
    const uint32_t qa  = sbase;
    const uint32_t k0a = sbase + QWRD*4;
    const uint32_t k1a = k0a + KWRD*4;
    const uint32_t v0a = k1a + KWRD*4;
    const uint32_t v1a = v0a + KWRD*4;

    const size_t kvcol = (size_t)h * HDd;

    {   // prologue: Q tile (2048 chunks) + KV tile 0 (1024 chunks each)
        #pragma unroll
        for (int i = 0; i < 8; i++) {
            int idx = tid + i * 256;
            int r = idx >> 4, c = idx & 15;
            uint32_t dof = (uint32_t)(r*ASTR + c*4) * 4u;
            size_t gq = (size_t)(b*Ss + q0 + r) * Dd + kvcol + c*8;
            CP_ASYNC16(qa + dof, g_Qh + gq);
        }
        #pragma unroll
        for (int i = 0; i < 4; i++) {
            int idx = tid + i * 256;
            int r = idx >> 4, c = idx & 15;
            uint32_t dof = (uint32_t)(r*ASTR + c*4) * 4u;
            size_t gk = (size_t)(b*Ss + r) * Dd + kvcol + c*8;
            CP_ASYNC16(k0a + dof, g_Kh + gk);
            CP_ASYNC16(v0a + dof, g_Vh + gk);
        }
        CP_COMMIT();
    }

    // ldmatrix lane address components (stride ASTR)
    const uint32_t q_off = (uint32_t)((warp*16 + (lane & 15)) * ASTR
                                      + ((lane >> 4) << 2)) * 4u;
    const uint32_t k_off = (uint32_t)(((lane & 7) + ((lane >> 4) << 3)) * ASTR
                                      + (((lane >> 3) & 1) << 2)) * 4u;
    const uint32_t v_off = (uint32_t)((lane & 15) * ASTR) * 4u
                         + ((uint32_t)(lane >> 4) << 4);

    float accO[16][4];
    #pragma unroll
    for (int nt = 0; nt < 16; nt++)
        #pragma unroll
        for (int e = 0; e < 4; e++) accO[nt][e] = 0.f;
    float m0 = -INFINITY, m1 = -INFINITY, l0 = 0.f, l1 = 0.f;

    const int g = lane >> 2;
    const int row0 = q0 + warp*16 + g;
    const int row1 = row0 + 8;
    const int nj = 2*qtile + 2;          // KV tiles covering rows [0, q0+128)

    for (int jt = 0; jt < nj; jt++) {
        CP_WAIT(0);
        __syncthreads();

        // prefetch next KV tile into the other buffer
        if (jt + 1 < nj) {
            const uint32_t ka = ((jt + 1) & 1) ? k1a : k0a;
            const uint32_t va = ((jt + 1) & 1) ? v1a : v0a;
            const int jrow = (jt + 1) * KTA;
            #pragma unroll
            for (int i = 0; i < 4; i++) {
                int idx = tid + i * 256;
                int r = idx >> 4, c = idx & 15;
                uint32_t dof = (uint32_t)(r*ASTR + c*4) * 4u;
                size_t gk = (size_t)(b*Ss + jrow + r) * Dd + kvcol + c*8;
                CP_ASYNC16(ka + dof, g_Kh + gk);
                CP_ASYNC16(va + dof, g_Vh + gk);
            }
            CP_COMMIT();
        }

        const uint32_t ka = (jt & 1) ? k1a : k0a;
        const uint32_t va = (jt & 1) ? v1a : v0a;
        const int j = jt * KTA;

        // ---- scores = Q K^T (warp: 16 x 64), 8 k16-chunks ----
        float sc[8][4];
        #pragma unroll
        for (int nt = 0; nt < 8; nt++)
            #pragma unroll
            for (int e = 0; e < 4; e++) sc[nt][e] = 0.f;

        #pragma unroll
        for (int ch = 0; ch < 8; ch++) {
            const uint32_t kso = (uint32_t)(ch * 8) * 4u;
            uint32_t a[4], bf[8][2];
            ldm_x4(a[0], a[1], a[2], a[3], qa + q_off + kso);
            #pragma unroll
            for (int p = 0; p < 4; p++)
                ldm_x4(bf[2*p][0], bf[2*p][1], bf[2*p+1][0], bf[2*p+1][1],
                       ka + k_off + kso + (uint32_t)(p*16*ASTR)*4u);
            #pragma unroll
            for (int nt = 0; nt < 8; nt++)
                mma_f16(sc[nt], a, bf[nt][0], bf[nt][1]);
        }

        // ---- scale + causal mask (tiles overlapping the diagonal) ----
        const bool diag = (j >= q0);
        #pragma unroll
        for (int nt = 0; nt < 8; nt++) {
            int col = j + nt*8 + t*2;
            sc[nt][0] *= ATTN_SCALE; sc[nt][1] *= ATTN_SCALE;
            sc[nt][2] *= ATTN_SCALE; sc[nt][3] *= ATTN_SCALE;
            if (diag) {
                if (col     > row0) sc[nt][0] = -INFINITY;
                if (col + 1 > row0) sc[nt][1] = -INFINITY;
                if (col     > row1) sc[nt][2] = -INFINITY;
                if (col + 1 > row1) sc[nt][3] = -INFINITY;
            }
        }

        // ---- online softmax (P in registers) ----
        float rm0 = -INFINITY, rm1 = -INFINITY;
        #pragma unroll
        for (int nt = 0; nt < 8; nt++) {
            rm0 = fmaxf(rm0, fmaxf(sc[nt][0], sc[nt][1]));
            rm1 = fmaxf(rm1, fmaxf(sc[nt][2], sc[nt][3]));
        }
        rm0 = fmaxf(rm0, __shfl_xor_sync(0xffffffffu, rm0, 1));
        rm0 = fmaxf(rm0, __shfl_xor_sync(0xffffffffu, rm0, 2));
        rm1 = fmaxf(rm1, __shfl_xor_sync(0xffffffffu, rm1, 1));
        rm1 = fmaxf(rm1, __shfl_xor_sync(0xffffffffu, rm1, 2));

        float m0n = fmaxf(m0, rm0), m1n = fmaxf(m1, rm1);
        float al0 = __expf(m0 - m0n), al1 = __expf(m1 - m1n);
        float sum0 = 0.f, sum1 = 0.f;
        uint32_t ph[8][2];
        #pragma unroll
        for (int nt = 0; nt < 8; nt++) {
            float p0 = __expf(sc[nt][0] - m0n);
            float p1 = __expf(sc[nt][1] - m0n);
            float p2 = __expf(sc[nt][2] - m1n);
            float p3 = __expf(sc[nt][3] - m1n);
            sum0 += p0 + p1; sum1 += p2 + p3;
            ph[nt][0] = pk2(p0, p1);
            ph[nt][1] = pk2(p2, p3);
        }
        sum0 += __shfl_xor_sync(0xffffffffu, sum0, 1);
        sum0 += __shfl_xor_sync(0xffffffffu, sum0, 2);
        sum1 += __shfl_xor_sync(0xffffffffu, sum1, 1);
        sum1 += __shfl_xor_sync(0xffffffffu, sum1, 2);
        l0 = l0 * al0 + sum0;
        l1 = l1 * al1 + sum1;
        m0 = m0n; m1 = m1n;
        #pragma unroll
        for (int nt = 0; nt < 16; nt++) {
            accO[nt][0] *= al0; accO[nt][1] *= al0;
            accO[nt][2] *= al1; accO[nt][3] *= al1;
        }

        // ---- O += P V (warp: 16 x 128); V via ldmatrix.x4.trans ----
        #pragma unroll
        for (int kc = 0; kc < 4; kc++) {
            const int n0 = kc * 2;
            uint32_t a[4];
            a[0] = ph[n0][0];     a[1] = ph[n0][1];
            a[2] = ph[n0+1][0];   a[3] = ph[n0+1][1];
            const uint32_t vb = va + (uint32_t)(kc*16*ASTR)*4u + v_off;
            #pragma unroll
            for (int np = 0; np < 8; np++) {
                uint32_t b0, b1, b2, b3;
                ldm_x4_t(b0, b1, b2, b3, vb + np*32);
                mma_f16(accO[2*np],   a, b0, b1);
                mma_f16(accO[2*np+1], a, b2, b3);
            }
        }
    }

    // ---- epilogue: normalize + pack to half ----
    float inv0 = 1.f / l0, inv1 = 1.f / l1;
    uint32_t* Aw = (uint32_t*)g_Ah;
    size_t ob0 = ((size_t)(b*Ss + q0 + warp*16 + g) * Dd + h * HDd) >> 1;
    size_t ob1 = ob0 + 4*Dd;
    #pragma unroll
    for (int nt = 0; nt < 16; nt++) {
        int cw = nt*4 + t;
        Aw[ob0 + cw] = pk2(accO[nt][0] * inv0, accO[nt][1] * inv0);
        Aw[ob1 + cw] = pk2(accO[nt][2] * inv1, accO[nt][3] * inv1);
    }
}

// ============================================================
extern "C" void kernel_launch(void* const* d_in, const int* in_sizes, int n_in,
                              void* d_out, int out_size)
{
    (void)in_sizes; (void)n_in; (void)out_size;
    const float* x    = (const float*)d_in[0];
    // d_in[1] = mask (unused -- causal implemented directly)
    const float* cosT = (const float*)d_in[2];
    const float* sinT = (const float*)d_in[3];
    const float* Wq   = (const float*)d_in[4];
    const float* Wk   = (const float*)d_in[5];
    const float* Wv   = (const float*)d_in[6];
    const float* Wo   = (const float*)d_in[7];
    float* out = (float*)d_out;

    __half *xh, *wh, *qh, *kh, *vh, *ah;
    cudaGetSymbolAddress((void**)&xh, g_Xh);
    cudaGetSymbolAddress((void**)&wh, g_Wh);
    cudaGetSymbolAddress((void**)&qh, g_Qh);
    cudaGetSymbolAddress((void**)&kh, g_Kh);
    cudaGetSymbolAddress((void**)&vh, g_Vh);
    cudaGetSymbolAddress((void**)&ah, g_Ah);
    __half* wqh = wh;
    __half* wkh = wh + (size_t)Dd*Dd;
    __half* wvh = wh + 2*(size_t)Dd*Dd;
    __half* woh = wh + 3*(size_t)Dd*Dd;

    // launches 0-2: packs (ncu -s 5 then lands on gemm_h below)
    pack_half<<<(MROWS*Dd/4)/256, 256>>>((const float4*)x, (uint32_t*)xh, MROWS*Dd/4);
    pack_half2<<<dim3((Dd*Dd/4)/256, 2), 256>>>((const float4*)Wq, (uint32_t*)wqh,
                                                (const float4*)Wk, (uint32_t*)wkh, Dd*Dd/4);
    pack_half2<<<dim3((Dd*Dd/4)/256, 2), 256>>>((const float4*)Wv, (uint32_t*)wvh,
                                                (const float4*)Wo, (uint32_t*)woh, Dd*Dd/4);

    cudaFuncSetAttribute(gemm_h, cudaFuncAttributeMaxDynamicSharedMemorySize, G_SMEM);
    dim3 gg(GN / 128, GM / 128);   // (16, 32)
    gemm_h<<<gg, 256, G_SMEM>>>(xh, wqh, qh, 1);    // launch 3
    gemm_h<<<gg, 256, G_SMEM>>>(xh, wkh, kh, 1);    // launch 4
    gemm_h<<<gg, 256, G_SMEM>>>(xh, wvh, vh, 1);    // launch 5  <- ncu capture

    int nrope = MROWS * Hh * 64;
    rope_h2<<<dim3(nrope / 256, 2), 256>>>(qh, kh, cosT, sinT);

    cudaFuncSetAttribute(attn_h, cudaFuncAttributeMaxDynamicSharedMemorySize, ATTN_SMEM);
    attn_h<<<dim3(Ss / QTA, Bb * Hh), 256, ATTN_SMEM>>>();

    gemm_h<<<gg, 256, G_SMEM>>>(ah, woh, out, 0);
}